// round 6
// baseline (speedup 1.0000x reference)
#include <cuda_runtime.h>
#include <cstdint>

#define U_N 10000
#define G_N 3000
#define I_N 8000
#define D 32
#define LMEM 20
#define B_N 4096
#define NNZ_UI 720000
#define NNZ_GI 440000
#define UI_N (U_N + I_N)   /* 18000 */
#define GI_N (G_N + I_N)   /* 11000 */
#define KSU 3              /* 79x3=237 blocks (<1 wave @2/SM) */
#define KSI 4              /* 63x4=252 blocks */
#define BR 128             /* rows per GEMM tile */
#define CDIV(a,b) (((a)+(b)-1)/(b))

#define ASTRIDE 36
#define XSTR 36
#define SMEM_GEMM ((2*BR*ASTRIDE + 2*32*XSTR) * 4)   /* 46080 B */

// ----------------- scratch -----------------
__device__ float d_ui0[UI_N*D], d_ui1[UI_N*D], d_ui2[UI_N*D], d_ui3[UI_N*D];
__device__ float d_gi0[GI_N*D], d_gi1[GI_N*D], d_gi2[GI_N*D], d_gi3[GI_N*D];
__device__ float d_cat[GI_N*D], d_cat2[GI_N*D];
__device__ float d_l1[G_N*D], d_l3[G_N*D];
// UI CSR
__device__ int   d_cnt[UI_N];
__device__ int   d_off[UI_N+1];
__device__ int   d_cur[UI_N];
__device__ int   d_scol[NNZ_UI];
__device__ float d_sval[NNZ_UI];
// GI CSR
__device__ int   d_cnt2[GI_N];
__device__ int   d_off2[GI_N+1];
__device__ int   d_cur2[GI_N];
__device__ int   d_scol2[NNZ_GI];
__device__ float d_sval2[NNZ_GI];

__device__ float d_uemean[U_N*D], d_iemean[I_N*D];
__device__ float d_iemb[I_N*D], d_gemb[G_N*D];
__device__ float d_parts[KSU*U_N*D];
__device__ float d_parts2[KSI*I_N*D];
__device__ float d_t1[U_N*D], d_accu[U_N*D];
__device__ float d_gul[G_N*D];
__device__ float d_wgt[2*G_N];
__device__ float d_gfin[G_N*D];
__device__ float d_it1[I_N*D], d_iacc[I_N*D];

// ----------------- small helpers -----------------
__global__ void k_copy2(const float* __restrict__ a, int na,
                        const float* __restrict__ b, int nb, float* __restrict__ dst) {
  int i = blockIdx.x*blockDim.x + threadIdx.x;
  if (i < na) dst[i] = a[i];
  else if (i < na+nb) dst[i] = b[i-na];
}

__global__ void k_copy_zero(const float* __restrict__ a, int na,
                            const float* __restrict__ b, int nb,
                            float* __restrict__ dst, int* __restrict__ cnt, int ncnt) {
  int i = blockIdx.x*blockDim.x + threadIdx.x;
  if (i < na) dst[i] = a[i];
  else if (i < na+nb) dst[i] = b[i-na];
  if (i < ncnt) cnt[i] = 0;
}

__global__ void k_zero_i(int* p, int n) {
  int i = blockIdx.x*blockDim.x + threadIdx.x;
  if (i < n) p[i] = 0;
}

__global__ void k_count(const int* __restrict__ rows, int nnz, int* cnt) {
  int i = blockIdx.x*blockDim.x + threadIdx.x;
  if (i < nnz) atomicAdd(&cnt[rows[i]], 1);
}

// single-block warp-shuffle exclusive scan
__global__ void __launch_bounds__(1024)
k_scan(const int* __restrict__ cnt, int* __restrict__ off,
       int* __restrict__ cur, int n) {
  __shared__ int warptot[32];
  int t = threadIdx.x;
  int lane = t & 31, w = t >> 5;
  int per = (n + 1023) / 1024;
  int beg = t * per, end = min(n, beg + per);
  int s = 0;
  for (int i = beg; i < end; ++i) s += cnt[i];
  int v = s;
  #pragma unroll
  for (int o = 1; o < 32; o <<= 1) {
    int u = __shfl_up_sync(0xffffffffu, v, o);
    if (lane >= o) v += u;
  }
  if (lane == 31) warptot[w] = v;
  __syncthreads();
  if (w == 0) {
    int x = warptot[lane];
    #pragma unroll
    for (int o = 1; o < 32; o <<= 1) {
      int u = __shfl_up_sync(0xffffffffu, x, o);
      if (lane >= o) x += u;
    }
    warptot[lane] = x;
  }
  __syncthreads();
  int run = (w ? warptot[w-1] : 0) + v - s;
  for (int i = beg; i < end; ++i) {
    int c = cnt[i];
    off[i] = run; cur[i] = run;
    run += c;
  }
  if (t == 0) off[n] = warptot[31];
}

__global__ void k_scatter(const int* __restrict__ rows, const int* __restrict__ cols,
                          const float* __restrict__ vals, int nnz,
                          int* cur, int* __restrict__ scol, float* __restrict__ sval) {
  int i = blockIdx.x*blockDim.x + threadIdx.x;
  if (i < nnz) {
    int r = rows[i];
    int p = atomicAdd(&cur[r], 1);
    scol[p] = cols[i];
    sval[p] = vals[i];
  }
}

// CSR SpMM: warp per row, lane per dim, MLP-4 batched loads
__global__ void k_spmm(const int* __restrict__ off, const int* __restrict__ scol,
                       const float* __restrict__ sval, const float* __restrict__ x,
                       float* __restrict__ y, int nrows) {
  int row = blockIdx.x*8 + (threadIdx.x >> 5);
  int lane = threadIdx.x & 31;
  if (row >= nrows) return;
  int s = off[row], e = off[row+1];
  float acc = 0.f;
  int p = s;
  for (; p + 4 <= e; p += 4) {
    int c0 = __ldg(&scol[p]),   c1 = __ldg(&scol[p+1]);
    int c2 = __ldg(&scol[p+2]), c3 = __ldg(&scol[p+3]);
    float v0 = __ldg(&sval[p]),   v1 = __ldg(&sval[p+1]);
    float v2 = __ldg(&sval[p+2]), v3 = __ldg(&sval[p+3]);
    float x0 = x[c0*D + lane], x1 = x[c1*D + lane];
    float x2 = x[c2*D + lane], x3 = x[c3*D + lane];
    acc = fmaf(v0, x0, acc); acc = fmaf(v1, x1, acc);
    acc = fmaf(v2, x2, acc); acc = fmaf(v3, x3, acc);
  }
  for (; p < e; ++p)
    acc = fmaf(__ldg(&sval[p]), x[__ldg(&scol[p])*D + lane], acc);
  y[row*D + lane] = acc;
}

__global__ void k_mean_ui() {
  int i = blockIdx.x*blockDim.x + threadIdx.x;
  if (i >= UI_N*D) return;
  float m = 0.25f*(d_ui0[i] + d_ui1[i] + d_ui2[i] + d_ui3[i]);
  if (i < U_N*D) d_uemean[i] = m;
  else d_iemean[i - U_N*D] = m;
}

__global__ void k_mean_gi() {
  int i = blockIdx.x*blockDim.x + threadIdx.x;
  if (i < G_N*D)
    d_gemb[i] = 0.25f*(d_gi0[i] + d_l1[i] + d_gi2[i] + d_l3[i]);
  if (i < I_N*D) {
    int j = G_N*D + i;
    d_iemb[i] = 0.25f*(d_gi0[j] + d_gi1[j] + d_gi2[j] + d_gi3[j]);
  }
}

// ----------------- dense GEMM: Parts[y][N,32] = A[N, kslice_y] @ X[kslice_y, 32] -----------------
// 512 threads. Warp = 8 rows (r8) x 4 d-quads (dq); lane owns 1 row x 8 d (d = 8*dq + j).
// f32x2 pairs run along k (acc.lo = even-k sum, acc.hi = odd-k sum) -> no {a,a} packing movs.
// X staged in smem d-major with permuted index d_idx = (d&7)*4 + (d>>3) so the 4 dq lanes
// hit 4 distinct bank groups (1 wavefront per X LDS.128). A rows stride 36 words -> the 8
// r8 lanes hit 8 distinct bank groups (1 wavefront per A LDS.128).

__device__ __forceinline__ void cpa16(uint32_t dst, const void* src, int bytes) {
  asm volatile("cp.async.cg.shared.global [%0], [%1], 16, %2;"
               :: "r"(dst), "l"(src), "r"(bytes));
}
__device__ __forceinline__ void cpa_commit() {
  asm volatile("cp.async.commit_group;");
}
__device__ __forceinline__ void cpa_wait1() {
  asm volatile("cp.async.wait_group 1;");
}

extern "C" __global__ void __launch_bounds__(512, 2)
k_gemm(const float* __restrict__ A, const float* __restrict__ X,
       float* __restrict__ Pbase, size_t pstride, int N, int K) {
  extern __shared__ float smem[];
  float* As = smem;                    // [2][BR][ASTRIDE]
  float* Xs = smem + 2*BR*ASTRIDE;     // [2][32 d_idx][XSTR]

  const int tid = threadIdx.x;
  const int wid = tid >> 5, lane = tid & 31;
  const int r8 = lane & 7, dq = lane >> 3;
  const int myrow = wid*8 + r8;                 // 0..127
  const int rowbase = blockIdx.x * BR;
  const int ks = gridDim.y;
  const int kchunk = (K + ks - 1) / ks;
  const int kbeg = blockIdx.y * kchunk;
  const int kend = min(K, kbeg + kchunk);
  const int nch = (kend - kbeg + 31) >> 5;

  uint32_t as_u32;
  asm("{ .reg .u64 t; cvta.to.shared.u64 t, %1; cvt.u32.u64 %0, t; }"
      : "=r"(as_u32) : "l"(smem));

  unsigned long long acc[8];
  #pragma unroll
  for (int j = 0; j < 8; ++j) acc[j] = 0ULL;

  // X staging regs: each thread carries 2 consecutive X elements (same k, d and d+1)
  float xr0 = 0.f, xr1 = 0.f;
  const int xe = tid * 2;
  const int xkk = xe >> 5;                      // k within chunk
  const int xd = xe & 31;                       // d (even)
  const int xidx0 = (xd & 7)*4 + (xd >> 3);
  const int xidx1 = (((xd+1) & 7))*4 + ((xd+1) >> 3);

  auto loadA = [&](int b, int k0) {
    #pragma unroll
    for (int s = 0; s < 2; ++s) {
      int id = tid + 512*s;
      int row = id >> 3, c = id & 7;
      int gr = rowbase + row;
      int kk = k0 + 4*c;
      int vb = 0;
      const float* src = A;
      if (gr < N && kk < kend) { vb = min(4, kend - kk)*4; src = A + (size_t)gr*K + kk; }
      cpa16(as_u32 + (uint32_t)((b*BR + row)*ASTRIDE + 4*c)*4, src, vb);
    }
  };
  auto loadXreg = [&](int k0) {
    int gk = k0 + xkk;
    if (gk < kend) {
      const float* p = X + (size_t)gk*D + xd;
      xr0 = p[0]; xr1 = p[1];
    } else { xr0 = 0.f; xr1 = 0.f; }
  };

  if (nch > 0) { loadA(0, kbeg); loadXreg(kbeg); }
  cpa_commit();

  for (int i = 0; i < nch; ++i) {
    int b = i & 1;
    if (i + 1 < nch) loadA((i+1) & 1, kbeg + (i+1)*32);
    cpa_commit();
    cpa_wait1();
    // stage X chunk i into smem buffer b (transposed, permuted d index)
    Xs[(b*32 + xidx0)*XSTR + xkk] = xr0;
    Xs[(b*32 + xidx1)*XSTR + xkk] = xr1;
    __syncthreads();
    if (i + 1 < nch) loadXreg(kbeg + (i+1)*32);

    const float* Ab = As + (size_t)b*BR*ASTRIDE;
    const float* Xb = Xs + (size_t)(b*32)*XSTR;

    #pragma unroll
    for (int kk4 = 0; kk4 < 8; ++kk4) {
      ulonglong2 av = *reinterpret_cast<const ulonglong2*>(&Ab[myrow*ASTRIDE + kk4*4]);
      #pragma unroll
      for (int j = 0; j < 8; ++j) {
        // d = 8*dq + j  ->  d_idx = j*4 + dq
        ulonglong2 xv = *reinterpret_cast<const ulonglong2*>(&Xb[(j*4 + dq)*XSTR + kk4*4]);
        asm("fma.rn.f32x2 %0, %1, %2, %0;" : "+l"(acc[j]) : "l"(av.x), "l"(xv.x));
        asm("fma.rn.f32x2 %0, %1, %2, %0;" : "+l"(acc[j]) : "l"(av.y), "l"(xv.y));
      }
    }
    __syncthreads();
  }

  int r = rowbase + myrow;
  if (r < N) {
    float o[8];
    #pragma unroll
    for (int j = 0; j < 8; ++j) {
      unsigned lo = (unsigned)(acc[j] & 0xffffffffULL);
      unsigned hi = (unsigned)(acc[j] >> 32);
      o[j] = __uint_as_float(lo) + __uint_as_float(hi);
    }
    float* P = Pbase + (size_t)blockIdx.y * pstride + (size_t)r*D + dq*8;
    *reinterpret_cast<float4*>(P)     = make_float4(o[0], o[1], o[2], o[3]);
    *reinterpret_cast<float4*>(P + 4) = make_float4(o[4], o[5], o[6], o[7]);
  }
}

// reduce ks partials (+ up to two extra addends) into dst
__global__ void k_red(float* __restrict__ dst, const float* __restrict__ b0,
                      const float* __restrict__ b1, const float* __restrict__ parts,
                      size_t pstride, int n, int ks) {
  int i = blockIdx.x*blockDim.x + threadIdx.x;
  if (i >= n) return;
  float s = 0.f;
  for (int p = 0; p < ks; ++p) s += parts[(size_t)p*pstride + i];
  if (b0) s += b0[i];
  if (b1) s += b1[i];
  dst[i] = s;
}

__global__ void k_gul(const int* __restrict__ gu, const float* __restrict__ gm) {
  int g = blockIdx.x*8 + (threadIdx.x >> 5);
  int lane = threadIdx.x & 31;
  if (g >= G_N) return;
  float acc = 0.f;
  #pragma unroll
  for (int l = 0; l < LMEM; ++l) {
    int u = __ldg(&gu[g*LMEM + l]);
    float m = __ldg(&gm[g*LMEM + l]);
    acc = fmaf(m, d_accu[u*D + lane], acc);
  }
  d_gul[g*D + lane] = acc;
}

__global__ void k_gate(const float* __restrict__ w1, const float* __restrict__ b1,
                       const float* __restrict__ w2, const float* __restrict__ b2) {
  int row = blockIdx.x*8 + (threadIdx.x >> 5);
  int lane = threadIdx.x & 31;
  if (row >= 2*G_N) return;
  const float* x = (row < G_N) ? &d_gemb[row*D] : &d_gul[(row - G_N)*D];
  float xv = x[lane];
  float h = b1[lane];
  #pragma unroll
  for (int k = 0; k < 32; ++k) {
    float xk = __shfl_sync(0xffffffffu, xv, k);
    h = fmaf(xk, w1[k*D + lane], h);
  }
  h = fmaxf(h, 0.f);
  float s = h * w2[lane];
  #pragma unroll
  for (int o = 16; o > 0; o >>= 1) s += __shfl_xor_sync(0xffffffffu, s, o);
  if (lane == 0) d_wgt[row] = 1.f/(1.f + expf(-(s + b2[0])));
}

__global__ void k_gfin() {
  int i = blockIdx.x*blockDim.x + threadIdx.x;
  if (i >= G_N*D) return;
  int g = i / D;
  d_gfin[i] = d_wgt[g]*d_gemb[i] + d_wgt[G_N + g]*d_gul[i];
}

__global__ void k_pred(const int* __restrict__ gin, const int* __restrict__ iin,
                       const float* __restrict__ w1, const float* __restrict__ b1,
                       const float* __restrict__ w2, const float* __restrict__ b2,
                       float* __restrict__ out) {
  int b = blockIdx.x*8 + (threadIdx.x >> 5);
  int lane = threadIdx.x & 31;
  if (b >= B_N) return;
  float e = d_gfin[gin[b]*D + lane] * d_iacc[iin[b]*D + lane];
  float z = 0.f;
  #pragma unroll
  for (int j = 0; j < 8; ++j) {
    float v = e * w1[lane*8 + j];
    #pragma unroll
    for (int o = 16; o > 0; o >>= 1) v += __shfl_xor_sync(0xffffffffu, v, o);
    if (lane == 0) z += fmaxf(v + b1[j], 0.f) * w2[j];
  }
  if (lane == 0) out[b] = 1.f/(1.f + expf(-(z + b2[0])));
}

// ----------------- host -----------------
template <typename T>
static T* symaddr(const void* sym) {
  void* p = nullptr;
  cudaGetSymbolAddress(&p, sym);
  return (T*)p;
}

extern "C" void kernel_launch(void* const* d_in, const int* in_sizes, int n_in,
                              void* d_out, int out_size) {
  const int*   gin       = (const int*)d_in[0];
  const int*   iin       = (const int*)d_in[1];
  const float* user_emb  = (const float*)d_in[2];
  const float* group_emb = (const float*)d_in[3];
  const float* item_emb  = (const float*)d_in[4];
  const int*   ui_rows   = (const int*)d_in[5];
  const int*   ui_cols   = (const int*)d_in[6];
  const float* ui_vals   = (const float*)d_in[7];
  const int*   gi_rows   = (const int*)d_in[8];
  const int*   gi_cols   = (const int*)d_in[9];
  const float* gi_vals   = (const float*)d_in[10];
  const float* ov_user   = (const float*)d_in[11];
  const float* ov_item   = (const float*)d_in[12];
  const int*   agu       = (const int*)d_in[13];
  const float* agm       = (const float*)d_in[14];
  const float* gate_w1   = (const float*)d_in[15];
  const float* gate_b1   = (const float*)d_in[16];
  const float* gate_w2   = (const float*)d_in[17];
  const float* gate_b2   = (const float*)d_in[18];
  const float* pred_w1   = (const float*)d_in[19];
  const float* pred_b1   = (const float*)d_in[20];
  const float* pred_w2   = (const float*)d_in[21];
  const float* pred_b2   = (const float*)d_in[22];
  float* out = (float*)d_out;

  cudaFuncSetAttribute(k_gemm, cudaFuncAttributeMaxDynamicSharedMemorySize, SMEM_GEMM);

  float *p_ui0 = symaddr<float>(d_ui0), *p_ui1 = symaddr<float>(d_ui1);
  float *p_ui2 = symaddr<float>(d_ui2), *p_ui3 = symaddr<float>(d_ui3);
  float *p_gi0 = symaddr<float>(d_gi0), *p_gi1 = symaddr<float>(d_gi1);
  float *p_gi2 = symaddr<float>(d_gi2), *p_gi3 = symaddr<float>(d_gi3);
  float *p_cat  = symaddr<float>(d_cat), *p_cat2 = symaddr<float>(d_cat2);
  float *p_l1  = symaddr<float>(d_l1),  *p_l3  = symaddr<float>(d_l3);
  int *p_cnt  = symaddr<int>(d_cnt),  *p_off  = symaddr<int>(d_off),  *p_cur  = symaddr<int>(d_cur);
  int *p_cnt2 = symaddr<int>(d_cnt2), *p_off2 = symaddr<int>(d_off2), *p_cur2 = symaddr<int>(d_cur2);
  int *p_scol = symaddr<int>(d_scol), *p_scol2 = symaddr<int>(d_scol2);
  float *p_sval = symaddr<float>(d_sval), *p_sval2 = symaddr<float>(d_sval2);
  float *p_uemean = symaddr<float>(d_uemean), *p_iemean = symaddr<float>(d_iemean);
  float *p_iemb = symaddr<float>(d_iemb);
  float *p_parts = symaddr<float>(d_parts), *p_parts2 = symaddr<float>(d_parts2);
  float *p_t1 = symaddr<float>(d_t1), *p_accu = symaddr<float>(d_accu);
  float *p_it1 = symaddr<float>(d_it1), *p_iacc = symaddr<float>(d_iacc);

  const size_t PSU = (size_t)U_N * D;
  const size_t PSI = (size_t)I_N * D;
  dim3 gemm_u(CDIV(U_N, BR), KSU);
  dim3 gemm_i(CDIV(I_N, BR), KSI);

  // second stream + events (leaked; kernel_launch called only a couple of times)
  cudaStream_t s1;
  cudaStreamCreateWithFlags(&s1, cudaStreamNonBlocking);
  cudaEvent_t ev_fork, ev_gicsr, ev_l1, ev_A, ev_mg, ev_C2;
  cudaEventCreateWithFlags(&ev_fork,  cudaEventDisableTiming);
  cudaEventCreateWithFlags(&ev_gicsr, cudaEventDisableTiming);
  cudaEventCreateWithFlags(&ev_l1,    cudaEventDisableTiming);
  cudaEventCreateWithFlags(&ev_A,     cudaEventDisableTiming);
  cudaEventCreateWithFlags(&ev_mg,    cudaEventDisableTiming);
  cudaEventCreateWithFlags(&ev_C2,    cudaEventDisableTiming);

  cudaEventRecord(ev_fork, 0);

  // ---- segment A1 (s0): launches #1..#4; #4 = representative GEMM for ncu ----
  k_copy_zero<<<CDIV((U_N+I_N)*D,256),256>>>(user_emb, U_N*D, item_emb, I_N*D, p_ui0, p_cnt, UI_N);
  k_count<<<CDIV(NNZ_UI,256),256>>>(ui_rows, NNZ_UI, p_cnt);
  k_scan<<<1,1024>>>(p_cnt, p_off, p_cur, UI_N);
  // HOOK (launch #4): steady-state GEMM on ov_user, truncated K; output overwritten later.
  k_gemm<<<gemm_u,512,SMEM_GEMM>>>(ov_user, ov_user, p_parts, PSU, U_N, 1536);

  // ---- segment B (s1): GI CSR build + l1 (independent of stage A) ----
  cudaStreamWaitEvent(s1, ev_fork, 0);
  k_zero_i<<<CDIV(GI_N,256),256,0,s1>>>(p_cnt2, GI_N);
  k_count<<<CDIV(NNZ_GI,256),256,0,s1>>>(gi_rows, NNZ_GI, p_cnt2);
  k_scan<<<1,1024,0,s1>>>(p_cnt2, p_off2, p_cur2, GI_N);
  k_scatter<<<CDIV(NNZ_GI,256),256,0,s1>>>(gi_rows, gi_cols, gi_vals, NNZ_GI, p_cur2, p_scol2, p_sval2);
  cudaEventRecord(ev_gicsr, s1);
  k_copy2<<<CDIV(GI_N*D,256),256,0,s1>>>(group_emb, G_N*D, item_emb, I_N*D, p_cat);
  k_spmm<<<CDIV(G_N,8),256,0,s1>>>(p_off2, p_scol2, p_sval2, p_cat, p_l1, G_N);
  cudaEventRecord(ev_l1, s1);

  // ---- segment A2 (s0): UI CSR + propagation ----
  k_scatter<<<CDIV(NNZ_UI,256),256>>>(ui_rows, ui_cols, ui_vals, NNZ_UI, p_cur, p_scol, p_sval);
  k_spmm<<<CDIV(UI_N,8),256>>>(p_off, p_scol, p_sval, p_ui0, p_ui1, UI_N);
  k_spmm<<<CDIV(UI_N,8),256>>>(p_off, p_scol, p_sval, p_ui1, p_ui2, UI_N);
  k_spmm<<<CDIV(UI_N,8),256>>>(p_off, p_scol, p_sval, p_ui2, p_ui3, UI_N);
  k_mean_ui<<<CDIV(UI_N*D,256),256>>>();
  cudaEventRecord(ev_A, 0);

  // ---- segment C (s1): user social GEMMs + group pooling ----
  cudaStreamWaitEvent(s1, ev_A, 0);
  k_gemm<<<gemm_u,512,SMEM_GEMM,s1>>>(ov_user, p_uemean, p_parts, PSU, U_N, U_N);
  k_red<<<CDIV(U_N*D,256),256,0,s1>>>(p_t1, nullptr, nullptr, p_parts, PSU, U_N*D, KSU);
  k_gemm<<<gemm_u,512,SMEM_GEMM,s1>>>(ov_user, p_t1, p_parts, PSU, U_N, U_N);
  k_red<<<CDIV(U_N*D,256),256,0,s1>>>(p_accu, p_uemean, p_t1, p_parts, PSU, U_N*D, KSU);
  k_gul<<<CDIV(G_N,8),256,0,s1>>>(agu, agm);

  // ---- segment D (s0): group-item propagation (overlaps C) ----
  k_copy2<<<CDIV(GI_N*D,256),256>>>(group_emb, G_N*D, p_iemean, I_N*D, p_gi0);
  cudaStreamWaitEvent(0, ev_gicsr, 0);
  k_spmm<<<CDIV(GI_N,8),256>>>(p_off2, p_scol2, p_sval2, p_gi0, p_gi1, GI_N);
  k_spmm<<<CDIV(GI_N,8),256>>>(p_off2, p_scol2, p_sval2, p_gi1, p_gi2, GI_N);
  k_spmm<<<CDIV(GI_N,8),256>>>(p_off2, p_scol2, p_sval2, p_gi2, p_gi3, GI_N);
  k_copy2<<<CDIV(GI_N*D,256),256>>>(group_emb, G_N*D, p_ui2 + U_N*D, I_N*D, p_cat2);
  k_spmm<<<CDIV(G_N,8),256>>>(p_off2, p_scol2, p_sval2, p_cat2, p_l3, G_N);
  cudaStreamWaitEvent(0, ev_l1, 0);
  k_mean_gi<<<CDIV(I_N*D,256),256>>>();
  cudaEventRecord(ev_mg, 0);

  // ---- segment E (s0): item social GEMMs ----
  k_gemm<<<gemm_i,512,SMEM_GEMM>>>(ov_item, p_iemb, p_parts2, PSI, I_N, I_N);
  k_red<<<CDIV(I_N*D,256),256>>>(p_it1, nullptr, nullptr, p_parts2, PSI, I_N*D, KSI);
  k_gemm<<<gemm_i,512,SMEM_GEMM>>>(ov_item, p_it1, p_parts2, PSI, I_N, I_N);
  k_red<<<CDIV(I_N*D,256),256>>>(p_iacc, p_iemb, p_it1, p_parts2, PSI, I_N*D, KSI);

  // ---- segment F (s1): gate (needs gemb from s0, gul from s1) ----
  cudaStreamWaitEvent(s1, ev_mg, 0);
  k_gate<<<CDIV(2*G_N,8),256,0,s1>>>(gate_w1, gate_b1, gate_w2, gate_b2);
  k_gfin<<<CDIV(G_N*D,256),256,0,s1>>>();
  cudaEventRecord(ev_C2, s1);

  // ---- segment G (s0): predict (joins s1) ----
  cudaStreamWaitEvent(0, ev_C2, 0);
  k_pred<<<CDIV(B_N,8),256>>>(gin, iin, pred_w1, pred_b1, pred_w2, pred_b2, out);
}

// round 7
// speedup vs baseline: 1.3605x; 1.3605x over previous
#include <cuda_runtime.h>
#include <cstdint>

#define U_N 10000
#define G_N 3000
#define I_N 8000
#define D 32
#define LMEM 20
#define B_N 4096
#define NNZ_UI 720000
#define NNZ_GI 440000
#define UI_N (U_N + I_N)
#define GI_N (G_N + I_N)
#define KSU 7              /* 20x7=140 blocks, 1 wave @1 CTA/SM */
#define KSI 9              /* 16x9=144 blocks */
#define BK 16              /* k per chunk */
#define BRG 512            /* rows per GEMM block */
#define CDIV(a,b) (((a)+(b)-1)/(b))
#define SMEM_GEMM (2*BK*BRG*4 + 2*BK*32*8)   /* 73728 B */

// ----------------- scratch -----------------
__device__ float d_ui0[UI_N*D], d_ui1[UI_N*D], d_ui2[UI_N*D], d_ui3[UI_N*D];
__device__ float d_gi0[GI_N*D], d_gi1[GI_N*D], d_gi2[GI_N*D], d_gi3[GI_N*D];
__device__ float d_cat[GI_N*D], d_cat2[GI_N*D];
__device__ float d_l1[G_N*D], d_l3[G_N*D];
__device__ int   d_cnt[UI_N];
__device__ int   d_off[UI_N+1];
__device__ int   d_cur[UI_N];
__device__ int   d_scol[NNZ_UI];
__device__ float d_sval[NNZ_UI];
__device__ int   d_cnt2[GI_N];
__device__ int   d_off2[GI_N+1];
__device__ int   d_cur2[GI_N];
__device__ int   d_scol2[NNZ_GI];
__device__ float d_sval2[NNZ_GI];

__device__ float d_uemean[U_N*D], d_iemean[I_N*D];
__device__ float d_iemb[I_N*D], d_gemb[G_N*D];
__device__ float d_parts[KSU*U_N*D];
__device__ float d_parts2[KSI*I_N*D];
__device__ float d_t1[U_N*D], d_accu[U_N*D];
__device__ float d_gul[G_N*D];
__device__ float d_wgt[2*G_N];
__device__ float d_gfin[G_N*D];
__device__ float d_it1[I_N*D], d_iacc[I_N*D];

// ----------------- small helpers -----------------
__global__ void k_copy2(const float* __restrict__ a, int na,
                        const float* __restrict__ b, int nb, float* __restrict__ dst) {
  int i = blockIdx.x*blockDim.x + threadIdx.x;
  if (i < na) dst[i] = a[i];
  else if (i < na+nb) dst[i] = b[i-na];
}

__global__ void k_copy_zero(const float* __restrict__ a, int na,
                            const float* __restrict__ b, int nb,
                            float* __restrict__ dst, int* __restrict__ cnt, int ncnt) {
  int i = blockIdx.x*blockDim.x + threadIdx.x;
  if (i < na) dst[i] = a[i];
  else if (i < na+nb) dst[i] = b[i-na];
  if (i < ncnt) cnt[i] = 0;
}

__global__ void k_zero_i(int* p, int n) {
  int i = blockIdx.x*blockDim.x + threadIdx.x;
  if (i < n) p[i] = 0;
}

__global__ void k_count(const int* __restrict__ rows, int nnz, int* cnt) {
  int i = blockIdx.x*blockDim.x + threadIdx.x;
  if (i < nnz) atomicAdd(&cnt[rows[i]], 1);
}

__global__ void __launch_bounds__(1024)
k_scan(const int* __restrict__ cnt, int* __restrict__ off,
       int* __restrict__ cur, int n) {
  __shared__ int warptot[32];
  int t = threadIdx.x;
  int lane = t & 31, w = t >> 5;
  int per = (n + 1023) / 1024;
  int beg = t * per, end = min(n, beg + per);
  int s = 0;
  for (int i = beg; i < end; ++i) s += cnt[i];
  int v = s;
  #pragma unroll
  for (int o = 1; o < 32; o <<= 1) {
    int u = __shfl_up_sync(0xffffffffu, v, o);
    if (lane >= o) v += u;
  }
  if (lane == 31) warptot[w] = v;
  __syncthreads();
  if (w == 0) {
    int x = warptot[lane];
    #pragma unroll
    for (int o = 1; o < 32; o <<= 1) {
      int u = __shfl_up_sync(0xffffffffu, x, o);
      if (lane >= o) x += u;
    }
    warptot[lane] = x;
  }
  __syncthreads();
  int run = (w ? warptot[w-1] : 0) + v - s;
  for (int i = beg; i < end; ++i) {
    int c = cnt[i];
    off[i] = run; cur[i] = run;
    run += c;
  }
  if (t == 0) off[n] = warptot[31];
}

__global__ void k_scatter(const int* __restrict__ rows, const int* __restrict__ cols,
                          const float* __restrict__ vals, int nnz,
                          int* cur, int* __restrict__ scol, float* __restrict__ sval) {
  int i = blockIdx.x*blockDim.x + threadIdx.x;
  if (i < nnz) {
    int r = rows[i];
    int p = atomicAdd(&cur[r], 1);
    scol[p] = cols[i];
    sval[p] = vals[i];
  }
}

__global__ void k_spmm(const int* __restrict__ off, const int* __restrict__ scol,
                       const float* __restrict__ sval, const float* __restrict__ x,
                       float* __restrict__ y, int nrows) {
  int row = blockIdx.x*8 + (threadIdx.x >> 5);
  int lane = threadIdx.x & 31;
  if (row >= nrows) return;
  int s = off[row], e = off[row+1];
  float acc = 0.f;
  int p = s;
  for (; p + 4 <= e; p += 4) {
    int c0 = __ldg(&scol[p]),   c1 = __ldg(&scol[p+1]);
    int c2 = __ldg(&scol[p+2]), c3 = __ldg(&scol[p+3]);
    float v0 = __ldg(&sval[p]),   v1 = __ldg(&sval[p+1]);
    float v2 = __ldg(&sval[p+2]), v3 = __ldg(&sval[p+3]);
    float x0 = x[c0*D + lane], x1 = x[c1*D + lane];
    float x2 = x[c2*D + lane], x3 = x[c3*D + lane];
    acc = fmaf(v0, x0, acc); acc = fmaf(v1, x1, acc);
    acc = fmaf(v2, x2, acc); acc = fmaf(v3, x3, acc);
  }
  for (; p < e; ++p)
    acc = fmaf(__ldg(&sval[p]), x[__ldg(&scol[p])*D + lane], acc);
  y[row*D + lane] = acc;
}

__global__ void k_mean_ui() {
  int i = blockIdx.x*blockDim.x + threadIdx.x;
  if (i >= UI_N*D) return;
  float m = 0.25f*(d_ui0[i] + d_ui1[i] + d_ui2[i] + d_ui3[i]);
  if (i < U_N*D) d_uemean[i] = m;
  else d_iemean[i - U_N*D] = m;
}

__global__ void k_mean_gi() {
  int i = blockIdx.x*blockDim.x + threadIdx.x;
  if (i < G_N*D)
    d_gemb[i] = 0.25f*(d_gi0[i] + d_l1[i] + d_gi2[i] + d_l3[i]);
  if (i < I_N*D) {
    int j = G_N*D + i;
    d_iemb[i] = 0.25f*(d_gi0[j] + d_gi1[j] + d_gi2[j] + d_gi3[j]);
  }
}

// ---------- dense GEMM: Parts[y][N,32] = A[N, kslice_y] @ X[kslice_y, 32] ----------
// 256 threads, 512-row tile, BK=16. A staged TRANSPOSED (At[k][512]) so row-pairs are
// adjacent -> f32x2 accumulators along rows with no packing movs. X staged pre-splatted
// {x,x}. Per k per thread: 2 A LDS.128 + 4 X LDS.128 + 32 FFMA2 (84% fma issue share).
extern "C" __global__ void __launch_bounds__(256, 1)
k_gemm(const float* __restrict__ A, const float* __restrict__ X,
       float* __restrict__ Pbase, size_t pstride, int N, int K) {
  extern __shared__ float smem[];
  float*  At = smem;                         // [2][BK][BRG]
  float2* Xd = (float2*)(smem + 2*BK*BRG);   // [2][BK][32] splats

  const int tid = threadIdx.x;
  const int warp = tid >> 5, lane = tid & 31;
  const int ro = lane >> 2, dq = lane & 3;
  const int rowbase = blockIdx.x * BRG;
  const int ks = gridDim.y;
  int kchunk = CDIV(CDIV(K, ks), BK) * BK;
  const int kbeg = blockIdx.y * kchunk;
  const int kend = min(K, kbeg + kchunk);
  const int nch = (kend > kbeg) ? (kend - kbeg) / BK : 0;   // all chunks full (K % 16 == 0)

  unsigned long long acc[4][8];
  #pragma unroll
  for (int rp = 0; rp < 4; ++rp)
    #pragma unroll
    for (int j = 0; j < 8; ++j) acc[rp][j] = 0ULL;

  float4 ar[8];                 // prefetch: 2 rows x 16 k
  float2 xr;                    // prefetch: 2 X elems
  const int r0 = tid * 2;
  const int xk = (tid*2) >> 5, xd = (tid*2) & 31;

  auto ldA = [&](int k0) {
    #pragma unroll
    for (int h = 0; h < 2; ++h) {
      int gr = rowbase + r0 + h;
      if (gr < N) {
        const float* src = A + (size_t)gr*K + k0;
        #pragma unroll
        for (int c = 0; c < 4; ++c) ar[h*4+c] = *(const float4*)(src + 4*c);
      } else {
        #pragma unroll
        for (int c = 0; c < 4; ++c) ar[h*4+c] = make_float4(0.f,0.f,0.f,0.f);
      }
    }
  };
  auto ldX = [&](int k0) {
    const float* p = X + (size_t)(k0 + xk)*D + xd;
    xr.x = p[0]; xr.y = p[1];
  };
  auto stA = [&](int b) {
    #pragma unroll
    for (int h = 0; h < 2; ++h)
      #pragma unroll
      for (int c = 0; c < 4; ++c) {
        float4 v = ar[h*4+c];
        float* p = At + (size_t)(b*BK + 4*c)*BRG + r0 + h;
        p[0] = v.x; p[BRG] = v.y; p[2*BRG] = v.z; p[3*BRG] = v.w;
      }
  };
  auto stX = [&](int b) {
    Xd[(b*BK + xk)*32 + xd]     = make_float2(xr.x, xr.x);
    Xd[(b*BK + xk)*32 + xd + 1] = make_float2(xr.y, xr.y);
  };

  if (nch > 0) {
    ldA(kbeg); ldX(kbeg);
    stA(0); stX(0);
    if (nch > 1) { ldA(kbeg + BK); ldX(kbeg + BK); }
    __syncthreads();

    for (int i = 0; i < nch; ++i) {
      int b = i & 1;
      if (i + 1 < nch) { stA(b ^ 1); stX(b ^ 1); }
      if (i + 2 < nch) { ldA(kbeg + (i+2)*BK); ldX(kbeg + (i+2)*BK); }

      const float*  Ab = At + (size_t)b*BK*BRG;
      const float2* Xb = Xd + (size_t)b*BK*32;
      #pragma unroll
      for (int kk = 0; kk < BK; ++kk) {
        const float* Ak = Ab + kk*BRG + warp*64 + ro*8;
        ulonglong2 a01 = *(const ulonglong2*)Ak;
        ulonglong2 a23 = *(const ulonglong2*)(Ak + 4);
        const ulonglong2* Xk = (const ulonglong2*)(Xb + kk*32 + dq*8);
        ulonglong2 x01 = Xk[0], x23 = Xk[1], x45 = Xk[2], x67 = Xk[3];
        unsigned long long av[4] = {a01.x, a01.y, a23.x, a23.y};
        unsigned long long xs[8] = {x01.x, x01.y, x23.x, x23.y, x45.x, x45.y, x67.x, x67.y};
        #pragma unroll
        for (int rp = 0; rp < 4; ++rp)
          #pragma unroll
          for (int j = 0; j < 8; ++j)
            asm("fma.rn.f32x2 %0, %1, %2, %0;" : "+l"(acc[rp][j]) : "l"(av[rp]), "l"(xs[j]));
      }
      __syncthreads();
    }
  }

  // epilogue: thread owns rows warp*64 + ro*8 + 2*rp (+1), d = dq*8 + j
  float* P = Pbase + (size_t)blockIdx.y * pstride;
  #pragma unroll
  for (int rp = 0; rp < 4; ++rp) {
    int r = rowbase + warp*64 + ro*8 + 2*rp;
    #pragma unroll
    for (int h = 0; h < 2; ++h) {
      if (r + h < N) {
        float o[8];
        #pragma unroll
        for (int j = 0; j < 8; ++j) {
          unsigned lo = (unsigned)(acc[rp][j] & 0xffffffffULL);
          unsigned hi = (unsigned)(acc[rp][j] >> 32);
          o[j] = h ? __uint_as_float(hi) : __uint_as_float(lo);
        }
        float* q = P + (size_t)(r+h)*D + dq*8;
        *(float4*)q       = make_float4(o[0], o[1], o[2], o[3]);
        *(float4*)(q + 4) = make_float4(o[4], o[5], o[6], o[7]);
      }
    }
  }
}

__global__ void k_red(float* __restrict__ dst, const float* __restrict__ b0,
                      const float* __restrict__ b1, const float* __restrict__ parts,
                      size_t pstride, int n, int ks) {
  int i = blockIdx.x*blockDim.x + threadIdx.x;
  if (i >= n) return;
  float s = 0.f;
  for (int p = 0; p < ks; ++p) s += parts[(size_t)p*pstride + i];
  if (b0) s += b0[i];
  if (b1) s += b1[i];
  dst[i] = s;
}

__global__ void k_gul(const int* __restrict__ gu, const float* __restrict__ gm) {
  int g = blockIdx.x*8 + (threadIdx.x >> 5);
  int lane = threadIdx.x & 31;
  if (g >= G_N) return;
  float acc = 0.f;
  #pragma unroll
  for (int l = 0; l < LMEM; ++l) {
    int u = __ldg(&gu[g*LMEM + l]);
    float m = __ldg(&gm[g*LMEM + l]);
    acc = fmaf(m, d_accu[u*D + lane], acc);
  }
  d_gul[g*D + lane] = acc;
}

__global__ void k_gate(const float* __restrict__ w1, const float* __restrict__ b1,
                       const float* __restrict__ w2, const float* __restrict__ b2) {
  int row = blockIdx.x*8 + (threadIdx.x >> 5);
  int lane = threadIdx.x & 31;
  if (row >= 2*G_N) return;
  const float* x = (row < G_N) ? &d_gemb[row*D] : &d_gul[(row - G_N)*D];
  float xv = x[lane];
  float h = b1[lane];
  #pragma unroll
  for (int k = 0; k < 32; ++k) {
    float xk = __shfl_sync(0xffffffffu, xv, k);
    h = fmaf(xk, w1[k*D + lane], h);
  }
  h = fmaxf(h, 0.f);
  float s = h * w2[lane];
  #pragma unroll
  for (int o = 16; o > 0; o >>= 1) s += __shfl_xor_sync(0xffffffffu, s, o);
  if (lane == 0) d_wgt[row] = 1.f/(1.f + expf(-(s + b2[0])));
}

__global__ void k_gfin() {
  int i = blockIdx.x*blockDim.x + threadIdx.x;
  if (i >= G_N*D) return;
  int g = i / D;
  d_gfin[i] = d_wgt[g]*d_gemb[i] + d_wgt[G_N + g]*d_gul[i];
}

__global__ void k_pred(const int* __restrict__ gin, const int* __restrict__ iin,
                       const float* __restrict__ w1, const float* __restrict__ b1,
                       const float* __restrict__ w2, const float* __restrict__ b2,
                       float* __restrict__ out) {
  int b = blockIdx.x*8 + (threadIdx.x >> 5);
  int lane = threadIdx.x & 31;
  if (b >= B_N) return;
  float e = d_gfin[gin[b]*D + lane] * d_iacc[iin[b]*D + lane];
  float z = 0.f;
  #pragma unroll
  for (int j = 0; j < 8; ++j) {
    float v = e * w1[lane*8 + j];
    #pragma unroll
    for (int o = 16; o > 0; o >>= 1) v += __shfl_xor_sync(0xffffffffu, v, o);
    if (lane == 0) z += fmaxf(v + b1[j], 0.f) * w2[j];
  }
  if (lane == 0) out[b] = 1.f/(1.f + expf(-(z + b2[0])));
}

// ----------------- host -----------------
template <typename T>
static T* symaddr(const void* sym) {
  void* p = nullptr;
  cudaGetSymbolAddress(&p, sym);
  return (T*)p;
}

extern "C" void kernel_launch(void* const* d_in, const int* in_sizes, int n_in,
                              void* d_out, int out_size) {
  const int*   gin       = (const int*)d_in[0];
  const int*   iin       = (const int*)d_in[1];
  const float* user_emb  = (const float*)d_in[2];
  const float* group_emb = (const float*)d_in[3];
  const float* item_emb  = (const float*)d_in[4];
  const int*   ui_rows   = (const int*)d_in[5];
  const int*   ui_cols   = (const int*)d_in[6];
  const float* ui_vals   = (const float*)d_in[7];
  const int*   gi_rows   = (const int*)d_in[8];
  const int*   gi_cols   = (const int*)d_in[9];
  const float* gi_vals   = (const float*)d_in[10];
  const float* ov_user   = (const float*)d_in[11];
  const float* ov_item   = (const float*)d_in[12];
  const int*   agu       = (const int*)d_in[13];
  const float* agm       = (const float*)d_in[14];
  const float* gate_w1   = (const float*)d_in[15];
  const float* gate_b1   = (const float*)d_in[16];
  const float* gate_w2   = (const float*)d_in[17];
  const float* gate_b2   = (const float*)d_in[18];
  const float* pred_w1   = (const float*)d_in[19];
  const float* pred_b1   = (const float*)d_in[20];
  const float* pred_w2   = (const float*)d_in[21];
  const float* pred_b2   = (const float*)d_in[22];
  float* out = (float*)d_out;

  cudaFuncSetAttribute(k_gemm, cudaFuncAttributeMaxDynamicSharedMemorySize, SMEM_GEMM);

  float *p_ui0 = symaddr<float>(d_ui0), *p_ui1 = symaddr<float>(d_ui1);
  float *p_ui2 = symaddr<float>(d_ui2), *p_ui3 = symaddr<float>(d_ui3);
  float *p_gi0 = symaddr<float>(d_gi0), *p_gi1 = symaddr<float>(d_gi1);
  float *p_gi2 = symaddr<float>(d_gi2), *p_gi3 = symaddr<float>(d_gi3);
  float *p_cat  = symaddr<float>(d_cat), *p_cat2 = symaddr<float>(d_cat2);
  float *p_l1  = symaddr<float>(d_l1),  *p_l3  = symaddr<float>(d_l3);
  int *p_cnt  = symaddr<int>(d_cnt),  *p_off  = symaddr<int>(d_off),  *p_cur  = symaddr<int>(d_cur);
  int *p_cnt2 = symaddr<int>(d_cnt2), *p_off2 = symaddr<int>(d_off2), *p_cur2 = symaddr<int>(d_cur2);
  int *p_scol = symaddr<int>(d_scol), *p_scol2 = symaddr<int>(d_scol2);
  float *p_sval = symaddr<float>(d_sval), *p_sval2 = symaddr<float>(d_sval2);
  float *p_uemean = symaddr<float>(d_uemean), *p_iemean = symaddr<float>(d_iemean);
  float *p_iemb = symaddr<float>(d_iemb);
  float *p_parts = symaddr<float>(d_parts), *p_parts2 = symaddr<float>(d_parts2);
  float *p_t1 = symaddr<float>(d_t1), *p_accu = symaddr<float>(d_accu);
  float *p_it1 = symaddr<float>(d_it1), *p_iacc = symaddr<float>(d_iacc);

  const size_t PSU = (size_t)U_N * D;
  const size_t PSI = (size_t)I_N * D;
  dim3 gemm_u(CDIV(U_N, BRG), KSU);
  dim3 gemm_i(CDIV(I_N, BRG), KSI);

  cudaStream_t s1;
  cudaStreamCreateWithFlags(&s1, cudaStreamNonBlocking);
  cudaEvent_t ev_fork, ev_gicsr, ev_l1, ev_A, ev_mg, ev_C2;
  cudaEventCreateWithFlags(&ev_fork,  cudaEventDisableTiming);
  cudaEventCreateWithFlags(&ev_gicsr, cudaEventDisableTiming);
  cudaEventCreateWithFlags(&ev_l1,    cudaEventDisableTiming);
  cudaEventCreateWithFlags(&ev_A,     cudaEventDisableTiming);
  cudaEventCreateWithFlags(&ev_mg,    cudaEventDisableTiming);
  cudaEventCreateWithFlags(&ev_C2,    cudaEventDisableTiming);

  cudaEventRecord(ev_fork, 0);

  // ---- segment A1 (s0): launches #1..#4; #4 = representative GEMM for ncu ----
  k_copy_zero<<<CDIV((U_N+I_N)*D,256),256>>>(user_emb, U_N*D, item_emb, I_N*D, p_ui0, p_cnt, UI_N);
  k_count<<<CDIV(NNZ_UI,256),256>>>(ui_rows, NNZ_UI, p_cnt);
  k_scan<<<1,1024>>>(p_cnt, p_off, p_cur, UI_N);
  // HOOK (launch #4): steady-state GEMM on ov_user, truncated K; output overwritten later.
  k_gemm<<<gemm_u,256,SMEM_GEMM>>>(ov_user, ov_user, p_parts, PSU, U_N, 1536);

  // ---- segment B (s1): GI CSR build + l1 ----
  cudaStreamWaitEvent(s1, ev_fork, 0);
  k_zero_i<<<CDIV(GI_N,256),256,0,s1>>>(p_cnt2, GI_N);
  k_count<<<CDIV(NNZ_GI,256),256,0,s1>>>(gi_rows, NNZ_GI, p_cnt2);
  k_scan<<<1,1024,0,s1>>>(p_cnt2, p_off2, p_cur2, GI_N);
  k_scatter<<<CDIV(NNZ_GI,256),256,0,s1>>>(gi_rows, gi_cols, gi_vals, NNZ_GI, p_cur2, p_scol2, p_sval2);
  cudaEventRecord(ev_gicsr, s1);
  k_copy2<<<CDIV(GI_N*D,256),256,0,s1>>>(group_emb, G_N*D, item_emb, I_N*D, p_cat);
  k_spmm<<<CDIV(G_N,8),256,0,s1>>>(p_off2, p_scol2, p_sval2, p_cat, p_l1, G_N);
  cudaEventRecord(ev_l1, s1);

  // ---- segment A2 (s0): UI CSR + propagation ----
  k_scatter<<<CDIV(NNZ_UI,256),256>>>(ui_rows, ui_cols, ui_vals, NNZ_UI, p_cur, p_scol, p_sval);
  k_spmm<<<CDIV(UI_N,8),256>>>(p_off, p_scol, p_sval, p_ui0, p_ui1, UI_N);
  k_spmm<<<CDIV(UI_N,8),256>>>(p_off, p_scol, p_sval, p_ui1, p_ui2, UI_N);
  k_spmm<<<CDIV(UI_N,8),256>>>(p_off, p_scol, p_sval, p_ui2, p_ui3, UI_N);
  k_mean_ui<<<CDIV(UI_N*D,256),256>>>();
  cudaEventRecord(ev_A, 0);

  // ---- segment C (s1): user social GEMMs + group pooling ----
  cudaStreamWaitEvent(s1, ev_A, 0);
  k_gemm<<<gemm_u,256,SMEM_GEMM,s1>>>(ov_user, p_uemean, p_parts, PSU, U_N, U_N);
  k_red<<<CDIV(U_N*D,256),256,0,s1>>>(p_t1, nullptr, nullptr, p_parts, PSU, U_N*D, KSU);
  k_gemm<<<gemm_u,256,SMEM_GEMM,s1>>>(ov_user, p_t1, p_parts, PSU, U_N, U_N);
  k_red<<<CDIV(U_N*D,256),256,0,s1>>>(p_accu, p_uemean, p_t1, p_parts, PSU, U_N*D, KSU);
  k_gul<<<CDIV(G_N,8),256,0,s1>>>(agu, agm);

  // ---- segment D (s0): group-item propagation (overlaps C) ----
  k_copy2<<<CDIV(GI_N*D,256),256>>>(group_emb, G_N*D, p_iemean, I_N*D, p_gi0);
  cudaStreamWaitEvent(0, ev_gicsr, 0);
  k_spmm<<<CDIV(GI_N,8),256>>>(p_off2, p_scol2, p_sval2, p_gi0, p_gi1, GI_N);
  k_spmm<<<CDIV(GI_N,8),256>>>(p_off2, p_scol2, p_sval2, p_gi1, p_gi2, GI_N);
  k_spmm<<<CDIV(GI_N,8),256>>>(p_off2, p_scol2, p_sval2, p_gi2, p_gi3, GI_N);
  k_copy2<<<CDIV(GI_N*D,256),256>>>(group_emb, G_N*D, p_ui2 + U_N*D, I_N*D, p_cat2);
  k_spmm<<<CDIV(G_N,8),256>>>(p_off2, p_scol2, p_sval2, p_cat2, p_l3, G_N);
  cudaStreamWaitEvent(0, ev_l1, 0);
  k_mean_gi<<<CDIV(I_N*D,256),256>>>();
  cudaEventRecord(ev_mg, 0);

  // ---- segment E (s0): item social GEMMs ----
  k_gemm<<<gemm_i,256,SMEM_GEMM>>>(ov_item, p_iemb, p_parts2, PSI, I_N, I_N);
  k_red<<<CDIV(I_N*D,256),256>>>(p_it1, nullptr, nullptr, p_parts2, PSI, I_N*D, KSI);
  k_gemm<<<gemm_i,256,SMEM_GEMM>>>(ov_item, p_it1, p_parts2, PSI, I_N, I_N);
  k_red<<<CDIV(I_N*D,256),256>>>(p_iacc, p_iemb, p_it1, p_parts2, PSI, I_N*D, KSI);

  // ---- segment F (s1): gate ----
  cudaStreamWaitEvent(s1, ev_mg, 0);
  k_gate<<<CDIV(2*G_N,8),256,0,s1>>>(gate_w1, gate_b1, gate_w2, gate_b2);
  k_gfin<<<CDIV(G_N*D,256),256,0,s1>>>();
  cudaEventRecord(ev_C2, s1);

  // ---- segment G (s0): predict ----
  cudaStreamWaitEvent(0, ev_C2, 0);
  k_pred<<<CDIV(B_N,8),256>>>(gin, iin, pred_w1, pred_b1, pred_w2, pred_b2, out);
}

// round 8
// speedup vs baseline: 1.6757x; 1.2317x over previous
#include <cuda_runtime.h>
#include <cstdint>

#define U_N 10000
#define G_N 3000
#define I_N 8000
#define D 32
#define LMEM 20
#define B_N 4096
#define NNZ_UI 720000
#define NNZ_GI 440000
#define UI_N (U_N + I_N)
#define GI_N (G_N + I_N)
#define KSU 14             /* 10x14=140 blocks, 1 wave @1 CTA/SM */
#define KSI 18             /* 8x18=144 blocks */
#define BK 8               /* k per chunk */
#define BRG 1024           /* rows per GEMM block */
#define CDIV(a,b) (((a)+(b)-1)/(b))
#define SMEM_GEMM (2*BK*BRG*4 + 2*BK*32*8)   /* 69632 B */

// ----------------- scratch -----------------
__device__ float d_ui0[UI_N*D], d_ui1[UI_N*D], d_ui2[UI_N*D], d_ui3[UI_N*D];
__device__ float d_gi0[GI_N*D], d_gi1[GI_N*D], d_gi2[GI_N*D], d_gi3[GI_N*D];
__device__ float d_cat[GI_N*D], d_cat2[GI_N*D];
__device__ float d_l1[G_N*D], d_l3[G_N*D];
__device__ int   d_cnt[UI_N];
__device__ int   d_off[UI_N+1];
__device__ int   d_cur[UI_N];
__device__ int   d_scol[NNZ_UI];
__device__ float d_sval[NNZ_UI];
__device__ int   d_cnt2[GI_N];
__device__ int   d_off2[GI_N+1];
__device__ int   d_cur2[GI_N];
__device__ int   d_scol2[NNZ_GI];
__device__ float d_sval2[NNZ_GI];

__device__ float d_uemean[U_N*D], d_iemean[I_N*D];
__device__ float d_iemb[I_N*D], d_gemb[G_N*D];
__device__ float d_parts[KSU*U_N*D];
__device__ float d_parts2[KSI*I_N*D];
__device__ float d_t1[U_N*D], d_accu[U_N*D];
__device__ float d_gul[G_N*D];
__device__ float d_wgt[2*G_N];
__device__ float d_gfin[G_N*D];
__device__ float d_it1[I_N*D], d_iacc[I_N*D];

// ----------------- small helpers -----------------
__global__ void k_copy2(const float* __restrict__ a, int na,
                        const float* __restrict__ b, int nb, float* __restrict__ dst) {
  int i = blockIdx.x*blockDim.x + threadIdx.x;
  if (i < na) dst[i] = a[i];
  else if (i < na+nb) dst[i] = b[i-na];
}

__global__ void k_copy_zero(const float* __restrict__ a, int na,
                            const float* __restrict__ b, int nb,
                            float* __restrict__ dst, int* __restrict__ cnt, int ncnt) {
  int i = blockIdx.x*blockDim.x + threadIdx.x;
  if (i < na) dst[i] = a[i];
  else if (i < na+nb) dst[i] = b[i-na];
  if (i < ncnt) cnt[i] = 0;
}

__global__ void k_zero_i(int* p, int n) {
  int i = blockIdx.x*blockDim.x + threadIdx.x;
  if (i < n) p[i] = 0;
}

__global__ void k_count(const int* __restrict__ rows, int nnz, int* cnt) {
  int i = blockIdx.x*blockDim.x + threadIdx.x;
  if (i < nnz) atomicAdd(&cnt[rows[i]], 1);
}

__global__ void __launch_bounds__(1024)
k_scan(const int* __restrict__ cnt, int* __restrict__ off,
       int* __restrict__ cur, int n) {
  __shared__ int warptot[32];
  int t = threadIdx.x;
  int lane = t & 31, w = t >> 5;
  int per = (n + 1023) / 1024;
  int beg = t * per, end = min(n, beg + per);
  int s = 0;
  for (int i = beg; i < end; ++i) s += cnt[i];
  int v = s;
  #pragma unroll
  for (int o = 1; o < 32; o <<= 1) {
    int u = __shfl_up_sync(0xffffffffu, v, o);
    if (lane >= o) v += u;
  }
  if (lane == 31) warptot[w] = v;
  __syncthreads();
  if (w == 0) {
    int x = warptot[lane];
    #pragma unroll
    for (int o = 1; o < 32; o <<= 1) {
      int u = __shfl_up_sync(0xffffffffu, x, o);
      if (lane >= o) x += u;
    }
    warptot[lane] = x;
  }
  __syncthreads();
  int run = (w ? warptot[w-1] : 0) + v - s;
  for (int i = beg; i < end; ++i) {
    int c = cnt[i];
    off[i] = run; cur[i] = run;
    run += c;
  }
  if (t == 0) off[n] = warptot[31];
}

__global__ void k_scatter(const int* __restrict__ rows, const int* __restrict__ cols,
                          const float* __restrict__ vals, int nnz,
                          int* cur, int* __restrict__ scol, float* __restrict__ sval) {
  int i = blockIdx.x*blockDim.x + threadIdx.x;
  if (i < nnz) {
    int r = rows[i];
    int p = atomicAdd(&cur[r], 1);
    scol[p] = cols[i];
    sval[p] = vals[i];
  }
}

__global__ void k_spmm(const int* __restrict__ off, const int* __restrict__ scol,
                       const float* __restrict__ sval, const float* __restrict__ x,
                       float* __restrict__ y, int nrows) {
  int row = blockIdx.x*8 + (threadIdx.x >> 5);
  int lane = threadIdx.x & 31;
  if (row >= nrows) return;
  int s = off[row], e = off[row+1];
  float acc = 0.f;
  int p = s;
  for (; p + 4 <= e; p += 4) {
    int c0 = __ldg(&scol[p]),   c1 = __ldg(&scol[p+1]);
    int c2 = __ldg(&scol[p+2]), c3 = __ldg(&scol[p+3]);
    float v0 = __ldg(&sval[p]),   v1 = __ldg(&sval[p+1]);
    float v2 = __ldg(&sval[p+2]), v3 = __ldg(&sval[p+3]);
    float x0 = x[c0*D + lane], x1 = x[c1*D + lane];
    float x2 = x[c2*D + lane], x3 = x[c3*D + lane];
    acc = fmaf(v0, x0, acc); acc = fmaf(v1, x1, acc);
    acc = fmaf(v2, x2, acc); acc = fmaf(v3, x3, acc);
  }
  for (; p < e; ++p)
    acc = fmaf(__ldg(&sval[p]), x[__ldg(&scol[p])*D + lane], acc);
  y[row*D + lane] = acc;
}

__global__ void k_mean_ui() {
  int i = blockIdx.x*blockDim.x + threadIdx.x;
  if (i >= UI_N*D) return;
  float m = 0.25f*(d_ui0[i] + d_ui1[i] + d_ui2[i] + d_ui3[i]);
  if (i < U_N*D) d_uemean[i] = m;
  else d_iemean[i - U_N*D] = m;
}

__global__ void k_mean_gi() {
  int i = blockIdx.x*blockDim.x + threadIdx.x;
  if (i < G_N*D)
    d_gemb[i] = 0.25f*(d_gi0[i] + d_l1[i] + d_gi2[i] + d_l3[i]);
  if (i < I_N*D) {
    int j = G_N*D + i;
    d_iemb[i] = 0.25f*(d_gi0[j] + d_gi1[j] + d_gi2[j] + d_gi3[j]);
  }
}

// ---------- dense GEMM: Parts[y][N,32] = A[N, kslice_y] @ X[kslice_y, 32] ----------
// 512 threads, 1024-row tile, BK=8. Thread = rows rg*4..+3 (rg=tid&255) x 16 d
// (dg=tid>>8). A transposed in smem (At[k][1024]) so 4 adjacent rows = one LDS.128,
// accumulators f32x2 along row pairs. X staged as dup pairs {x,x}. Per kk:
// 32 FFMA2 + 1 A LDS.128 + 8 X LDS.128 -> ~78% fma issue share, 16 warps/SM.
extern "C" __global__ void __launch_bounds__(512, 1)
k_gemm(const float* __restrict__ A, const float* __restrict__ X,
       float* __restrict__ Pbase, size_t pstride, int N, int K) {
  extern __shared__ float smem[];
  float*  At = smem;                         // [2][BK][BRG]
  float2* Xs = (float2*)(smem + 2*BK*BRG);   // [2][BK][32] dup pairs

  const int tid = threadIdx.x;
  const int rg = tid & 255;
  const int dg = tid >> 8;                   // 0..1
  const int rowbase = blockIdx.x * BRG;
  const int ks = gridDim.y;
  int kchunk = CDIV(CDIV(K, ks), BK) * BK;
  const int kbeg = blockIdx.y * kchunk;
  const int kend = min(K, kbeg + kchunk);
  const int nch = (kend > kbeg) ? (kend - kbeg) / BK : 0;  // chunks always full

  unsigned long long acc[2][16];
  #pragma unroll
  for (int rp = 0; rp < 2; ++rp)
    #pragma unroll
    for (int j = 0; j < 16; ++j) acc[rp][j] = 0ULL;

  float4 ar[4];      // 2 rows x 8 k staging
  float  xr = 0.f;
  const int lr = tid * 2;                    // local rows lr, lr+1
  const int xk = tid >> 5, xd = tid & 31;    // X: threads 0..255 load 1 float

  auto ldA = [&](int k0) {
    #pragma unroll
    for (int h = 0; h < 2; ++h) {
      int gr = rowbase + lr + h;
      if (gr < N) {
        const float* src = A + (size_t)gr*K + k0;
        ar[h*2]   = *(const float4*)src;
        ar[h*2+1] = *(const float4*)(src + 4);
      } else {
        ar[h*2]   = make_float4(0.f,0.f,0.f,0.f);
        ar[h*2+1] = make_float4(0.f,0.f,0.f,0.f);
      }
    }
  };
  auto ldX = [&](int k0) {
    if (tid < 256) xr = X[(size_t)(k0 + xk)*D + xd];
  };
  auto stA = [&](int b) {
    #pragma unroll
    for (int q = 0; q < 2; ++q) {
      const float* f0 = (const float*)&ar[q];
      const float* f1 = (const float*)&ar[2+q];
      #pragma unroll
      for (int c = 0; c < 4; ++c) {
        int k = q*4 + c;
        *(float2*)(At + (size_t)(b*BK + k)*BRG + lr) = make_float2(f0[c], f1[c]);
      }
    }
  };
  auto stX = [&](int b) {
    if (tid < 256) Xs[(b*BK + xk)*32 + xd] = make_float2(xr, xr);
  };

  if (nch > 0) {
    ldA(kbeg); ldX(kbeg);
    stA(0); stX(0);
    if (nch > 1) { ldA(kbeg + BK); ldX(kbeg + BK); }
    __syncthreads();

    for (int i = 0; i < nch; ++i) {
      int b = i & 1;
      if (i + 1 < nch) { stA(b ^ 1); stX(b ^ 1); }
      if (i + 2 < nch) { ldA(kbeg + (i+2)*BK); ldX(kbeg + (i+2)*BK); }

      const float*  Ab = At + (size_t)b*BK*BRG;
      const float2* Xb = Xs + (size_t)b*BK*32;
      #pragma unroll
      for (int kk = 0; kk < BK; ++kk) {
        ulonglong2 av = *(const ulonglong2*)(Ab + kk*BRG + rg*4);
        const ulonglong2* Xk = (const ulonglong2*)(Xb + kk*32 + dg*16);
        #pragma unroll
        for (int c = 0; c < 8; ++c) {
          ulonglong2 xv = Xk[c];
          asm("fma.rn.f32x2 %0, %1, %2, %0;" : "+l"(acc[0][2*c])   : "l"(av.x), "l"(xv.x));
          asm("fma.rn.f32x2 %0, %1, %2, %0;" : "+l"(acc[0][2*c+1]) : "l"(av.x), "l"(xv.y));
          asm("fma.rn.f32x2 %0, %1, %2, %0;" : "+l"(acc[1][2*c])   : "l"(av.y), "l"(xv.x));
          asm("fma.rn.f32x2 %0, %1, %2, %0;" : "+l"(acc[1][2*c+1]) : "l"(av.y), "l"(xv.y));
        }
      }
      __syncthreads();
    }
  }

  // epilogue: rows rg*4 + 2*rp + h, d = dg*16 + j
  float* P = Pbase + (size_t)blockIdx.y * pstride;
  #pragma unroll
  for (int rp = 0; rp < 2; ++rp) {
    #pragma unroll
    for (int h = 0; h < 2; ++h) {
      int r = rowbase + rg*4 + 2*rp + h;
      if (r < N) {
        float o[16];
        #pragma unroll
        for (int j = 0; j < 16; ++j) {
          unsigned lo = (unsigned)(acc[rp][j] & 0xffffffffULL);
          unsigned hi = (unsigned)(acc[rp][j] >> 32);
          o[j] = h ? __uint_as_float(hi) : __uint_as_float(lo);
        }
        float* q = P + (size_t)r*D + dg*16;
        *(float4*)q        = make_float4(o[0],  o[1],  o[2],  o[3]);
        *(float4*)(q + 4)  = make_float4(o[4],  o[5],  o[6],  o[7]);
        *(float4*)(q + 8)  = make_float4(o[8],  o[9],  o[10], o[11]);
        *(float4*)(q + 12) = make_float4(o[12], o[13], o[14], o[15]);
      }
    }
  }
}

__global__ void k_red(float* __restrict__ dst, const float* __restrict__ b0,
                      const float* __restrict__ b1, const float* __restrict__ parts,
                      size_t pstride, int n, int ks) {
  int i = blockIdx.x*blockDim.x + threadIdx.x;
  if (i >= n) return;
  float s = 0.f;
  for (int p = 0; p < ks; ++p) s += parts[(size_t)p*pstride + i];
  if (b0) s += b0[i];
  if (b1) s += b1[i];
  dst[i] = s;
}

__global__ void k_gul(const int* __restrict__ gu, const float* __restrict__ gm) {
  int g = blockIdx.x*8 + (threadIdx.x >> 5);
  int lane = threadIdx.x & 31;
  if (g >= G_N) return;
  float acc = 0.f;
  #pragma unroll
  for (int l = 0; l < LMEM; ++l) {
    int u = __ldg(&gu[g*LMEM + l]);
    float m = __ldg(&gm[g*LMEM + l]);
    acc = fmaf(m, d_accu[u*D + lane], acc);
  }
  d_gul[g*D + lane] = acc;
}

__global__ void k_gate(const float* __restrict__ w1, const float* __restrict__ b1,
                       const float* __restrict__ w2, const float* __restrict__ b2) {
  int row = blockIdx.x*8 + (threadIdx.x >> 5);
  int lane = threadIdx.x & 31;
  if (row >= 2*G_N) return;
  const float* x = (row < G_N) ? &d_gemb[row*D] : &d_gul[(row - G_N)*D];
  float xv = x[lane];
  float h = b1[lane];
  #pragma unroll
  for (int k = 0; k < 32; ++k) {
    float xk = __shfl_sync(0xffffffffu, xv, k);
    h = fmaf(xk, w1[k*D + lane], h);
  }
  h = fmaxf(h, 0.f);
  float s = h * w2[lane];
  #pragma unroll
  for (int o = 16; o > 0; o >>= 1) s += __shfl_xor_sync(0xffffffffu, s, o);
  if (lane == 0) d_wgt[row] = 1.f/(1.f + expf(-(s + b2[0])));
}

__global__ void k_gfin() {
  int i = blockIdx.x*blockDim.x + threadIdx.x;
  if (i >= G_N*D) return;
  int g = i / D;
  d_gfin[i] = d_wgt[g]*d_gemb[i] + d_wgt[G_N + g]*d_gul[i];
}

__global__ void k_pred(const int* __restrict__ gin, const int* __restrict__ iin,
                       const float* __restrict__ w1, const float* __restrict__ b1,
                       const float* __restrict__ w2, const float* __restrict__ b2,
                       float* __restrict__ out) {
  int b = blockIdx.x*8 + (threadIdx.x >> 5);
  int lane = threadIdx.x & 31;
  if (b >= B_N) return;
  float e = d_gfin[gin[b]*D + lane] * d_iacc[iin[b]*D + lane];
  float z = 0.f;
  #pragma unroll
  for (int j = 0; j < 8; ++j) {
    float v = e * w1[lane*8 + j];
    #pragma unroll
    for (int o = 16; o > 0; o >>= 1) v += __shfl_xor_sync(0xffffffffu, v, o);
    if (lane == 0) z += fmaxf(v + b1[j], 0.f) * w2[j];
  }
  if (lane == 0) out[b] = 1.f/(1.f + expf(-(z + b2[0])));
}

// ----------------- host -----------------
template <typename T>
static T* symaddr(const void* sym) {
  void* p = nullptr;
  cudaGetSymbolAddress(&p, sym);
  return (T*)p;
}

extern "C" void kernel_launch(void* const* d_in, const int* in_sizes, int n_in,
                              void* d_out, int out_size) {
  const int*   gin       = (const int*)d_in[0];
  const int*   iin       = (const int*)d_in[1];
  const float* user_emb  = (const float*)d_in[2];
  const float* group_emb = (const float*)d_in[3];
  const float* item_emb  = (const float*)d_in[4];
  const int*   ui_rows   = (const int*)d_in[5];
  const int*   ui_cols   = (const int*)d_in[6];
  const float* ui_vals   = (const float*)d_in[7];
  const int*   gi_rows   = (const int*)d_in[8];
  const int*   gi_cols   = (const int*)d_in[9];
  const float* gi_vals   = (const float*)d_in[10];
  const float* ov_user   = (const float*)d_in[11];
  const float* ov_item   = (const float*)d_in[12];
  const int*   agu       = (const int*)d_in[13];
  const float* agm       = (const float*)d_in[14];
  const float* gate_w1   = (const float*)d_in[15];
  const float* gate_b1   = (const float*)d_in[16];
  const float* gate_w2   = (const float*)d_in[17];
  const float* gate_b2   = (const float*)d_in[18];
  const float* pred_w1   = (const float*)d_in[19];
  const float* pred_b1   = (const float*)d_in[20];
  const float* pred_w2   = (const float*)d_in[21];
  const float* pred_b2   = (const float*)d_in[22];
  float* out = (float*)d_out;

  cudaFuncSetAttribute(k_gemm, cudaFuncAttributeMaxDynamicSharedMemorySize, SMEM_GEMM);

  float *p_ui0 = symaddr<float>(d_ui0), *p_ui1 = symaddr<float>(d_ui1);
  float *p_ui2 = symaddr<float>(d_ui2), *p_ui3 = symaddr<float>(d_ui3);
  float *p_gi0 = symaddr<float>(d_gi0), *p_gi1 = symaddr<float>(d_gi1);
  float *p_gi2 = symaddr<float>(d_gi2), *p_gi3 = symaddr<float>(d_gi3);
  float *p_cat  = symaddr<float>(d_cat), *p_cat2 = symaddr<float>(d_cat2);
  float *p_l1  = symaddr<float>(d_l1),  *p_l3  = symaddr<float>(d_l3);
  int *p_cnt  = symaddr<int>(d_cnt),  *p_off  = symaddr<int>(d_off),  *p_cur  = symaddr<int>(d_cur);
  int *p_cnt2 = symaddr<int>(d_cnt2), *p_off2 = symaddr<int>(d_off2), *p_cur2 = symaddr<int>(d_cur2);
  int *p_scol = symaddr<int>(d_scol), *p_scol2 = symaddr<int>(d_scol2);
  float *p_sval = symaddr<float>(d_sval), *p_sval2 = symaddr<float>(d_sval2);
  float *p_uemean = symaddr<float>(d_uemean), *p_iemean = symaddr<float>(d_iemean);
  float *p_iemb = symaddr<float>(d_iemb);
  float *p_parts = symaddr<float>(d_parts), *p_parts2 = symaddr<float>(d_parts2);
  float *p_t1 = symaddr<float>(d_t1), *p_accu = symaddr<float>(d_accu);
  float *p_it1 = symaddr<float>(d_it1), *p_iacc = symaddr<float>(d_iacc);

  const size_t PSU = (size_t)U_N * D;
  const size_t PSI = (size_t)I_N * D;
  dim3 gemm_u(CDIV(U_N, BRG), KSU);
  dim3 gemm_i(CDIV(I_N, BRG), KSI);

  cudaStream_t s1;
  cudaStreamCreateWithFlags(&s1, cudaStreamNonBlocking);
  cudaEvent_t ev_fork, ev_gicsr, ev_l1, ev_A, ev_mg, ev_C2;
  cudaEventCreateWithFlags(&ev_fork,  cudaEventDisableTiming);
  cudaEventCreateWithFlags(&ev_gicsr, cudaEventDisableTiming);
  cudaEventCreateWithFlags(&ev_l1,    cudaEventDisableTiming);
  cudaEventCreateWithFlags(&ev_A,     cudaEventDisableTiming);
  cudaEventCreateWithFlags(&ev_mg,    cudaEventDisableTiming);
  cudaEventCreateWithFlags(&ev_C2,    cudaEventDisableTiming);

  cudaEventRecord(ev_fork, 0);

  // ---- segment A1 (s0): launches #1..#4; #4 = representative GEMM for ncu ----
  k_copy_zero<<<CDIV((U_N+I_N)*D,256),256>>>(user_emb, U_N*D, item_emb, I_N*D, p_ui0, p_cnt, UI_N);
  k_count<<<CDIV(NNZ_UI,256),256>>>(ui_rows, NNZ_UI, p_cnt);
  k_scan<<<1,1024>>>(p_cnt, p_off, p_cur, UI_N);
  // HOOK (launch #4): steady-state GEMM on ov_user, truncated K; output overwritten later.
  k_gemm<<<gemm_u,512,SMEM_GEMM>>>(ov_user, ov_user, p_parts, PSU, U_N, 1536);

  // ---- segment B (s1): GI CSR build + l1 ----
  cudaStreamWaitEvent(s1, ev_fork, 0);
  k_zero_i<<<CDIV(GI_N,256),256,0,s1>>>(p_cnt2, GI_N);
  k_count<<<CDIV(NNZ_GI,256),256,0,s1>>>(gi_rows, NNZ_GI, p_cnt2);
  k_scan<<<1,1024,0,s1>>>(p_cnt2, p_off2, p_cur2, GI_N);
  k_scatter<<<CDIV(NNZ_GI,256),256,0,s1>>>(gi_rows, gi_cols, gi_vals, NNZ_GI, p_cur2, p_scol2, p_sval2);
  cudaEventRecord(ev_gicsr, s1);
  k_copy2<<<CDIV(GI_N*D,256),256,0,s1>>>(group_emb, G_N*D, item_emb, I_N*D, p_cat);
  k_spmm<<<CDIV(G_N,8),256,0,s1>>>(p_off2, p_scol2, p_sval2, p_cat, p_l1, G_N);
  cudaEventRecord(ev_l1, s1);

  // ---- segment A2 (s0): UI CSR + propagation ----
  k_scatter<<<CDIV(NNZ_UI,256),256>>>(ui_rows, ui_cols, ui_vals, NNZ_UI, p_cur, p_scol, p_sval);
  k_spmm<<<CDIV(UI_N,8),256>>>(p_off, p_scol, p_sval, p_ui0, p_ui1, UI_N);
  k_spmm<<<CDIV(UI_N,8),256>>>(p_off, p_scol, p_sval, p_ui1, p_ui2, UI_N);
  k_spmm<<<CDIV(UI_N,8),256>>>(p_off, p_scol, p_sval, p_ui2, p_ui3, UI_N);
  k_mean_ui<<<CDIV(UI_N*D,256),256>>>();
  cudaEventRecord(ev_A, 0);

  // ---- segment C (s1): user social GEMMs + group pooling ----
  cudaStreamWaitEvent(s1, ev_A, 0);
  k_gemm<<<gemm_u,512,SMEM_GEMM,s1>>>(ov_user, p_uemean, p_parts, PSU, U_N, U_N);
  k_red<<<CDIV(U_N*D,256),256,0,s1>>>(p_t1, nullptr, nullptr, p_parts, PSU, U_N*D, KSU);
  k_gemm<<<gemm_u,512,SMEM_GEMM,s1>>>(ov_user, p_t1, p_parts, PSU, U_N, U_N);
  k_red<<<CDIV(U_N*D,256),256,0,s1>>>(p_accu, p_uemean, p_t1, p_parts, PSU, U_N*D, KSU);
  k_gul<<<CDIV(G_N,8),256,0,s1>>>(agu, agm);

  // ---- segment D (s0): group-item propagation (overlaps C) ----
  k_copy2<<<CDIV(GI_N*D,256),256>>>(group_emb, G_N*D, p_iemean, I_N*D, p_gi0);
  cudaStreamWaitEvent(0, ev_gicsr, 0);
  k_spmm<<<CDIV(GI_N,8),256>>>(p_off2, p_scol2, p_sval2, p_gi0, p_gi1, GI_N);
  k_spmm<<<CDIV(GI_N,8),256>>>(p_off2, p_scol2, p_sval2, p_gi1, p_gi2, GI_N);
  k_spmm<<<CDIV(GI_N,8),256>>>(p_off2, p_scol2, p_sval2, p_gi2, p_gi3, GI_N);
  k_copy2<<<CDIV(GI_N*D,256),256>>>(group_emb, G_N*D, p_ui2 + U_N*D, I_N*D, p_cat2);
  k_spmm<<<CDIV(G_N,8),256>>>(p_off2, p_scol2, p_sval2, p_cat2, p_l3, G_N);
  cudaStreamWaitEvent(0, ev_l1, 0);
  k_mean_gi<<<CDIV(I_N*D,256),256>>>();
  cudaEventRecord(ev_mg, 0);

  // ---- segment E (s0): item social GEMMs ----
  k_gemm<<<gemm_i,512,SMEM_GEMM>>>(ov_item, p_iemb, p_parts2, PSI, I_N, I_N);
  k_red<<<CDIV(I_N*D,256),256>>>(p_it1, nullptr, nullptr, p_parts2, PSI, I_N*D, KSI);
  k_gemm<<<gemm_i,512,SMEM_GEMM>>>(ov_item, p_it1, p_parts2, PSI, I_N, I_N);
  k_red<<<CDIV(I_N*D,256),256>>>(p_iacc, p_iemb, p_it1, p_parts2, PSI, I_N*D, KSI);

  // ---- segment F (s1): gate ----
  cudaStreamWaitEvent(s1, ev_mg, 0);
  k_gate<<<CDIV(2*G_N,8),256,0,s1>>>(gate_w1, gate_b1, gate_w2, gate_b2);
  k_gfin<<<CDIV(G_N*D,256),256,0,s1>>>();
  cudaEventRecord(ev_C2, s1);

  // ---- segment G (s0): predict ----
  cudaStreamWaitEvent(0, ev_C2, 0);
  k_pred<<<CDIV(B_N,8),256>>>(gin, iin, pred_w1, pred_b1, pred_w2, pred_b2, out);
}

// round 10
// speedup vs baseline: 2.3846x; 1.4230x over previous
#include <cuda_runtime.h>
#include <cuda_bf16.h>
#include <cstdint>

#define U_N 10000
#define G_N 3000
#define I_N 8000
#define D 32
#define LMEM 20
#define B_N 4096
#define NNZ_UI 720000
#define NNZ_GI 440000
#define UI_N (U_N + I_N)
#define GI_N (G_N + I_N)
#define KSU 3
#define KSI 4
#define TILEM 128
#define TILEK 64
#define ASTR 72                         /* bf16 row stride (144 B) */
#define CDIV(a,b) (((a)+(b)-1)/(b))

/* smem byte offsets */
#define SM_AH 0
#define SM_AL (TILEM*ASTR*2)            /* 18432 */
#define SM_XH (2*TILEM*ASTR*2)          /* 36864 */
#define SM_XL (SM_XH + 32*ASTR*2)       /* 41472 */
#define SMEM_MMA (SM_XL + 32*ASTR*2)    /* 46080 */

// ----------------- scratch -----------------
__device__ float d_ui0[UI_N*D], d_ui1[UI_N*D], d_ui2[UI_N*D], d_ui3[UI_N*D];
__device__ float d_gi0[GI_N*D], d_gi1[GI_N*D], d_gi2[GI_N*D], d_gi3[GI_N*D];
__device__ float d_cat[GI_N*D], d_cat2[GI_N*D];
__device__ float d_l1[G_N*D], d_l3[G_N*D];
__device__ int   d_cnt[UI_N];
__device__ int   d_off[UI_N+1];
__device__ int   d_cur[UI_N];
__device__ int   d_scol[NNZ_UI];
__device__ float d_sval[NNZ_UI];
__device__ int   d_cnt2[GI_N];
__device__ int   d_off2[GI_N+1];
__device__ int   d_cur2[GI_N];
__device__ int   d_scol2[NNZ_GI];
__device__ float d_sval2[NNZ_GI];

__device__ float d_uemean[U_N*D], d_iemean[I_N*D];
__device__ float d_iemb[I_N*D], d_gemb[G_N*D];
__device__ float d_parts[KSU*U_N*D];
__device__ float d_parts2[KSI*I_N*D];
__device__ float d_t1[U_N*D], d_accu[U_N*D];
__device__ float d_gul[G_N*D];
__device__ float d_wgt[2*G_N];
__device__ float d_gfin[G_N*D];
__device__ float d_it1[I_N*D], d_iacc[I_N*D];

// ----------------- helpers -----------------
__device__ __forceinline__ void split2(float a, float b, uint32_t& h, uint32_t& l) {
  __nv_bfloat162 hb = __floats2bfloat162_rn(a, b);
  float ha = __bfloat162float(hb.x), hc = __bfloat162float(hb.y);
  __nv_bfloat162 lb = __floats2bfloat162_rn(a - ha, b - hc);
  h = *(uint32_t*)&hb; l = *(uint32_t*)&lb;
}

#define MMA16816(c, a, b0v, b1v) \
  asm volatile("mma.sync.aligned.m16n8k16.row.col.f32.bf16.bf16.f32 " \
    "{%0,%1,%2,%3}, {%4,%5,%6,%7}, {%8,%9}, {%0,%1,%2,%3};" \
    : "+f"((c)[0]), "+f"((c)[1]), "+f"((c)[2]), "+f"((c)[3]) \
    : "r"((a)[0]), "r"((a)[1]), "r"((a)[2]), "r"((a)[3]), "r"(b0v), "r"(b1v))

// ----------------- small kernels -----------------
__global__ void k_copy2(const float* __restrict__ a, int na,
                        const float* __restrict__ b, int nb, float* __restrict__ dst) {
  int i = blockIdx.x*blockDim.x + threadIdx.x;
  if (i < na) dst[i] = a[i];
  else if (i < na+nb) dst[i] = b[i-na];
}

__global__ void k_copy_zero(const float* __restrict__ a, int na,
                            const float* __restrict__ b, int nb,
                            float* __restrict__ dst, int* __restrict__ cnt, int ncnt) {
  int i = blockIdx.x*blockDim.x + threadIdx.x;
  if (i < na) dst[i] = a[i];
  else if (i < na+nb) dst[i] = b[i-na];
  if (i < ncnt) cnt[i] = 0;
}

__global__ void k_zero_i(int* p, int n) {
  int i = blockIdx.x*blockDim.x + threadIdx.x;
  if (i < n) p[i] = 0;
}

__global__ void k_count(const int* __restrict__ rows, int nnz, int* cnt) {
  int i = blockIdx.x*blockDim.x + threadIdx.x;
  if (i < nnz) atomicAdd(&cnt[rows[i]], 1);
}

__global__ void __launch_bounds__(1024)
k_scan(const int* __restrict__ cnt, int* __restrict__ off,
       int* __restrict__ cur, int n) {
  __shared__ int warptot[32];
  int t = threadIdx.x;
  int lane = t & 31, w = t >> 5;
  int per = (n + 1023) / 1024;
  int beg = t * per, end = min(n, beg + per);
  int s = 0;
  for (int i = beg; i < end; ++i) s += cnt[i];
  int v = s;
  #pragma unroll
  for (int o = 1; o < 32; o <<= 1) {
    int u = __shfl_up_sync(0xffffffffu, v, o);
    if (lane >= o) v += u;
  }
  if (lane == 31) warptot[w] = v;
  __syncthreads();
  if (w == 0) {
    int x = warptot[lane];
    #pragma unroll
    for (int o = 1; o < 32; o <<= 1) {
      int u = __shfl_up_sync(0xffffffffu, x, o);
      if (lane >= o) x += u;
    }
    warptot[lane] = x;
  }
  __syncthreads();
  int run = (w ? warptot[w-1] : 0) + v - s;
  for (int i = beg; i < end; ++i) {
    int c = cnt[i];
    off[i] = run; cur[i] = run;
    run += c;
  }
  if (t == 0) off[n] = warptot[31];
}

__global__ void k_scatter(const int* __restrict__ rows, const int* __restrict__ cols,
                          const float* __restrict__ vals, int nnz,
                          int* cur, int* __restrict__ scol, float* __restrict__ sval) {
  int i = blockIdx.x*blockDim.x + threadIdx.x;
  if (i < nnz) {
    int r = rows[i];
    int p = atomicAdd(&cur[r], 1);
    scol[p] = cols[i];
    sval[p] = vals[i];
  }
}

__global__ void k_spmm(const int* __restrict__ off, const int* __restrict__ scol,
                       const float* __restrict__ sval, const float* __restrict__ x,
                       float* __restrict__ y, int nrows) {
  int row = blockIdx.x*8 + (threadIdx.x >> 5);
  int lane = threadIdx.x & 31;
  if (row >= nrows) return;
  int s = off[row], e = off[row+1];
  float acc = 0.f;
  int p = s;
  for (; p + 4 <= e; p += 4) {
    int c0 = __ldg(&scol[p]),   c1 = __ldg(&scol[p+1]);
    int c2 = __ldg(&scol[p+2]), c3 = __ldg(&scol[p+3]);
    float v0 = __ldg(&sval[p]),   v1 = __ldg(&sval[p+1]);
    float v2 = __ldg(&sval[p+2]), v3 = __ldg(&sval[p+3]);
    float x0 = x[c0*D + lane], x1 = x[c1*D + lane];
    float x2 = x[c2*D + lane], x3 = x[c3*D + lane];
    acc = fmaf(v0, x0, acc); acc = fmaf(v1, x1, acc);
    acc = fmaf(v2, x2, acc); acc = fmaf(v3, x3, acc);
  }
  for (; p < e; ++p)
    acc = fmaf(__ldg(&sval[p]), x[__ldg(&scol[p])*D + lane], acc);
  y[row*D + lane] = acc;
}

__global__ void k_mean_ui() {
  int i = blockIdx.x*blockDim.x + threadIdx.x;
  if (i >= UI_N*D) return;
  float m = 0.25f*(d_ui0[i] + d_ui1[i] + d_ui2[i] + d_ui3[i]);
  if (i < U_N*D) d_uemean[i] = m;
  else d_iemean[i - U_N*D] = m;
}

__global__ void k_mean_gi() {
  int i = blockIdx.x*blockDim.x + threadIdx.x;
  if (i < G_N*D)
    d_gemb[i] = 0.25f*(d_gi0[i] + d_l1[i] + d_gi2[i] + d_l3[i]);
  if (i < I_N*D) {
    int j = G_N*D + i;
    d_iemb[i] = 0.25f*(d_gi0[j] + d_gi1[j] + d_gi2[j] + d_gi3[j]);
  }
}

// ---------- bf16 mma.sync GEMM: Parts[y][N,32] = A[N,kslice] @ X[kslice,32] ----------
// hi/lo split: D += Ah*Xh + Al*Xh + Ah*Xl. 256 thr, 128-row tile, 64-k chunks.
// A smem [row][k] bf16 stride 72; X smem transposed [n][k] bf16 stride 72.
extern "C" __global__ void __launch_bounds__(256, 2)
k_gemm(const float* __restrict__ A, const float* __restrict__ X,
       float* __restrict__ Pbase, size_t pstride, int N, int K) {
  extern __shared__ char smem[];
  const int tid = threadIdx.x;
  const int w = tid >> 5, lane = tid & 31;
  const int rowbase = blockIdx.x * TILEM;
  const int ks = gridDim.y;
  const int kchunk = CDIV(CDIV(K, ks), TILEK) * TILEK;
  const int kbeg = blockIdx.y * kchunk;
  const int kend = min(K, kbeg + kchunk);
  const int nch = (kend > kbeg) ? CDIV(kend - kbeg, TILEK) : 0;

  // staging assignment
  const int arow = tid >> 1;            // 0..127
  const int ahalf = tid & 1;            // k offset 32*ahalf
  const int xn = tid & 31;              // X col
  const int xw = tid >> 5;              // X k-slice: xw*8..+7

  float av[32];
  float xv[8];
  float acc[4][4];
  #pragma unroll
  for (int t = 0; t < 4; ++t)
    #pragma unroll
    for (int j = 0; j < 4; ++j) acc[t][j] = 0.f;

  auto ldAB = [&](int k0) {
    int gr = rowbase + arow;
    int kk = k0 + 32*ahalf;
    if (gr < N) {
      #pragma unroll
      for (int c = 0; c < 8; ++c) {
        int k = kk + 4*c;
        if (k + 4 <= kend) {
          float4 v = *(const float4*)(A + (size_t)gr*K + k);
          av[4*c] = v.x; av[4*c+1] = v.y; av[4*c+2] = v.z; av[4*c+3] = v.w;
        } else {
          #pragma unroll
          for (int j = 0; j < 4; ++j)
            av[4*c+j] = (k + j < kend) ? A[(size_t)gr*K + k + j] : 0.f;
        }
      }
    } else {
      #pragma unroll
      for (int j = 0; j < 32; ++j) av[j] = 0.f;
    }
    #pragma unroll
    for (int j = 0; j < 8; ++j) {
      int k = k0 + xw*8 + j;
      xv[j] = (k < kend) ? X[(size_t)k*D + xn] : 0.f;
    }
  };

  auto stAB = [&]() {
    #pragma unroll
    for (int j = 0; j < 16; ++j) {
      uint32_t h, l;
      split2(av[2*j], av[2*j+1], h, l);
      uint32_t off = (uint32_t)(arow*ASTR + 32*ahalf + 2*j) * 2;
      *(uint32_t*)(smem + SM_AH + off) = h;
      *(uint32_t*)(smem + SM_AL + off) = l;
    }
    #pragma unroll
    for (int j = 0; j < 4; ++j) {
      uint32_t h, l;
      split2(xv[2*j], xv[2*j+1], h, l);
      uint32_t off = (uint32_t)(xn*ASTR + xw*8 + 2*j) * 2;
      *(uint32_t*)(smem + SM_XH + off) = h;
      *(uint32_t*)(smem + SM_XL + off) = l;
    }
  };

  if (nch > 0) {
    ldAB(kbeg);
    stAB();
    __syncthreads();
    for (int i = 0; i < nch; ++i) {
      if (i + 1 < nch) ldAB(kbeg + (i+1)*TILEK);

      // compute chunk from smem
      #pragma unroll
      for (int s = 0; s < 4; ++s) {
        int kb = 16*s;
        int r0 = w*16 + (lane >> 2);
        int kc = kb + 2*(lane & 3);
        uint32_t oa = (uint32_t)(r0*ASTR + kc)*2;
        uint32_t ah[4], al[4];
        ah[0] = *(uint32_t*)(smem + SM_AH + oa);
        ah[1] = *(uint32_t*)(smem + SM_AH + oa + 8*ASTR*2);
        ah[2] = *(uint32_t*)(smem + SM_AH + oa + 16);
        ah[3] = *(uint32_t*)(smem + SM_AH + oa + 8*ASTR*2 + 16);
        al[0] = *(uint32_t*)(smem + SM_AL + oa);
        al[1] = *(uint32_t*)(smem + SM_AL + oa + 8*ASTR*2);
        al[2] = *(uint32_t*)(smem + SM_AL + oa + 16);
        al[3] = *(uint32_t*)(smem + SM_AL + oa + 8*ASTR*2 + 16);
        #pragma unroll
        for (int t = 0; t < 4; ++t) {
          int n0 = t*8 + (lane >> 2);
          uint32_t ob = (uint32_t)(n0*ASTR + kc)*2;
          uint32_t bh0 = *(uint32_t*)(smem + SM_XH + ob);
          uint32_t bh1 = *(uint32_t*)(smem + SM_XH + ob + 16);
          uint32_t bl0 = *(uint32_t*)(smem + SM_XL + ob);
          uint32_t bl1 = *(uint32_t*)(smem + SM_XL + ob + 16);
          MMA16816(acc[t], ah, bh0, bh1);
          MMA16816(acc[t], al, bh0, bh1);
          MMA16816(acc[t], ah, bl0, bl1);
        }
      }
      __syncthreads();
      if (i + 1 < nch) { stAB(); __syncthreads(); }
    }
  }

  // epilogue: c0,c1 -> (row, col..col+1); c2,c3 -> (row+8, ...)
  float* P = Pbase + (size_t)blockIdx.y * pstride;
  int rr = rowbase + w*16 + (lane >> 2);
  int cc = (lane & 3)*2;
  #pragma unroll
  for (int t = 0; t < 4; ++t) {
    if (rr < N)
      *(float2*)(P + (size_t)rr*D + t*8 + cc) = make_float2(acc[t][0], acc[t][1]);
    if (rr + 8 < N)
      *(float2*)(P + (size_t)(rr+8)*D + t*8 + cc) = make_float2(acc[t][2], acc[t][3]);
  }
}

__global__ void k_red(float* __restrict__ dst, const float* __restrict__ b0,
                      const float* __restrict__ b1, const float* __restrict__ parts,
                      size_t pstride, int n, int ks) {
  int i = blockIdx.x*blockDim.x + threadIdx.x;
  if (i >= n) return;
  float s = 0.f;
  for (int p = 0; p < ks; ++p) s += parts[(size_t)p*pstride + i];
  if (b0) s += b0[i];
  if (b1) s += b1[i];
  dst[i] = s;
}

__global__ void k_gul(const int* __restrict__ gu, const float* __restrict__ gm) {
  int g = blockIdx.x*8 + (threadIdx.x >> 5);
  int lane = threadIdx.x & 31;
  if (g >= G_N) return;
  float acc = 0.f;
  #pragma unroll
  for (int l = 0; l < LMEM; ++l) {
    int u = __ldg(&gu[g*LMEM + l]);
    float m = __ldg(&gm[g*LMEM + l]);
    acc = fmaf(m, d_accu[u*D + lane], acc);
  }
  d_gul[g*D + lane] = acc;
}

__global__ void k_gate(const float* __restrict__ w1, const float* __restrict__ b1,
                       const float* __restrict__ w2, const float* __restrict__ b2) {
  int row = blockIdx.x*8 + (threadIdx.x >> 5);
  int lane = threadIdx.x & 31;
  if (row >= 2*G_N) return;
  const float* x = (row < G_N) ? &d_gemb[row*D] : &d_gul[(row - G_N)*D];
  float xv = x[lane];
  float h = b1[lane];
  #pragma unroll
  for (int k = 0; k < 32; ++k) {
    float xk = __shfl_sync(0xffffffffu, xv, k);
    h = fmaf(xk, w1[k*D + lane], h);
  }
  h = fmaxf(h, 0.f);
  float s = h * w2[lane];
  #pragma unroll
  for (int o = 16; o > 0; o >>= 1) s += __shfl_xor_sync(0xffffffffu, s, o);
  if (lane == 0) d_wgt[row] = 1.f/(1.f + expf(-(s + b2[0])));
}

__global__ void k_gfin() {
  int i = blockIdx.x*blockDim.x + threadIdx.x;
  if (i >= G_N*D) return;
  int g = i / D;
  d_gfin[i] = d_wgt[g]*d_gemb[i] + d_wgt[G_N + g]*d_gul[i];
}

__global__ void k_pred(const int* __restrict__ gin, const int* __restrict__ iin,
                       const float* __restrict__ w1, const float* __restrict__ b1,
                       const float* __restrict__ w2, const float* __restrict__ b2,
                       float* __restrict__ out) {
  int b = blockIdx.x*8 + (threadIdx.x >> 5);
  int lane = threadIdx.x & 31;
  if (b >= B_N) return;
  float e = d_gfin[gin[b]*D + lane] * d_iacc[iin[b]*D + lane];
  float z = 0.f;
  #pragma unroll
  for (int j = 0; j < 8; ++j) {
    float v = e * w1[lane*8 + j];
    #pragma unroll
    for (int o = 16; o > 0; o >>= 1) v += __shfl_xor_sync(0xffffffffu, v, o);
    if (lane == 0) z += fmaxf(v + b1[j], 0.f) * w2[j];
  }
  if (lane == 0) out[b] = 1.f/(1.f + expf(-(z + b2[0])));
}

// ----------------- host -----------------
template <typename T>
static T* symaddr(const void* sym) {
  void* p = nullptr;
  cudaGetSymbolAddress(&p, sym);
  return (T*)p;
}

extern "C" void kernel_launch(void* const* d_in, const int* in_sizes, int n_in,
                              void* d_out, int out_size) {
  const int*   gin       = (const int*)d_in[0];
  const int*   iin       = (const int*)d_in[1];
  const float* user_emb  = (const float*)d_in[2];
  const float* group_emb = (const float*)d_in[3];
  const float* item_emb  = (const float*)d_in[4];
  const int*   ui_rows   = (const int*)d_in[5];
  const int*   ui_cols   = (const int*)d_in[6];
  const float* ui_vals   = (const float*)d_in[7];
  const int*   gi_rows   = (const int*)d_in[8];
  const int*   gi_cols   = (const int*)d_in[9];
  const float* gi_vals   = (const float*)d_in[10];
  const float* ov_user   = (const float*)d_in[11];
  const float* ov_item   = (const float*)d_in[12];
  const int*   agu       = (const int*)d_in[13];
  const float* agm       = (const float*)d_in[14];
  const float* gate_w1   = (const float*)d_in[15];
  const float* gate_b1   = (const float*)d_in[16];
  const float* gate_w2   = (const float*)d_in[17];
  const float* gate_b2   = (const float*)d_in[18];
  const float* pred_w1   = (const float*)d_in[19];
  const float* pred_b1   = (const float*)d_in[20];
  const float* pred_w2   = (const float*)d_in[21];
  const float* pred_b2   = (const float*)d_in[22];
  float* out = (float*)d_out;

  cudaFuncSetAttribute(k_gemm, cudaFuncAttributeMaxDynamicSharedMemorySize, SMEM_MMA);

  float *p_ui0 = symaddr<float>(d_ui0), *p_ui1 = symaddr<float>(d_ui1);
  float *p_ui2 = symaddr<float>(d_ui2), *p_ui3 = symaddr<float>(d_ui3);
  float *p_gi0 = symaddr<float>(d_gi0), *p_gi1 = symaddr<float>(d_gi1);
  float *p_gi2 = symaddr<float>(d_gi2), *p_gi3 = symaddr<float>(d_gi3);
  float *p_cat  = symaddr<float>(d_cat), *p_cat2 = symaddr<float>(d_cat2);
  float *p_l1  = symaddr<float>(d_l1),  *p_l3  = symaddr<float>(d_l3);
  int *p_cnt  = symaddr<int>(d_cnt),  *p_off  = symaddr<int>(d_off),  *p_cur  = symaddr<int>(d_cur);
  int *p_cnt2 = symaddr<int>(d_cnt2), *p_off2 = symaddr<int>(d_off2), *p_cur2 = symaddr<int>(d_cur2);
  int *p_scol = symaddr<int>(d_scol), *p_scol2 = symaddr<int>(d_scol2);
  float *p_sval = symaddr<float>(d_sval), *p_sval2 = symaddr<float>(d_sval2);
  float *p_uemean = symaddr<float>(d_uemean), *p_iemean = symaddr<float>(d_iemean);
  float *p_iemb = symaddr<float>(d_iemb);
  float *p_parts = symaddr<float>(d_parts), *p_parts2 = symaddr<float>(d_parts2);
  float *p_t1 = symaddr<float>(d_t1), *p_accu = symaddr<float>(d_accu);
  float *p_it1 = symaddr<float>(d_it1), *p_iacc = symaddr<float>(d_iacc);

  const size_t PSU = (size_t)U_N * D;
  const size_t PSI = (size_t)I_N * D;
  dim3 gemm_u(CDIV(U_N, TILEM), KSU);
  dim3 gemm_i(CDIV(I_N, TILEM), KSI);

  cudaStream_t s1;
  cudaStreamCreateWithFlags(&s1, cudaStreamNonBlocking);
  cudaEvent_t ev_fork, ev_gicsr, ev_l1, ev_A, ev_mg, ev_C2;
  cudaEventCreateWithFlags(&ev_fork,  cudaEventDisableTiming);
  cudaEventCreateWithFlags(&ev_gicsr, cudaEventDisableTiming);
  cudaEventCreateWithFlags(&ev_l1,    cudaEventDisableTiming);
  cudaEventCreateWithFlags(&ev_A,     cudaEventDisableTiming);
  cudaEventCreateWithFlags(&ev_mg,    cudaEventDisableTiming);
  cudaEventCreateWithFlags(&ev_C2,    cudaEventDisableTiming);

  cudaEventRecord(ev_fork, 0);

  // ---- segment A1 (s0): launches #1..#4; #4 = representative GEMM for ncu ----
  k_copy_zero<<<CDIV((U_N+I_N)*D,256),256>>>(user_emb, U_N*D, item_emb, I_N*D, p_ui0, p_cnt, UI_N);
  k_count<<<CDIV(NNZ_UI,256),256>>>(ui_rows, NNZ_UI, p_cnt);
  k_scan<<<1,1024>>>(p_cnt, p_off, p_cur, UI_N);
  // HOOK (launch #4): steady-state MMA GEMM on ov_user, truncated K; output overwritten later.
  k_gemm<<<gemm_u,256,SMEM_MMA>>>(ov_user, ov_user, p_parts, PSU, U_N, 1536);

  // ---- segment B (s1): GI CSR build + l1 ----
  cudaStreamWaitEvent(s1, ev_fork, 0);
  k_zero_i<<<CDIV(GI_N,256),256,0,s1>>>(p_cnt2, GI_N);
  k_count<<<CDIV(NNZ_GI,256),256,0,s1>>>(gi_rows, NNZ_GI, p_cnt2);
  k_scan<<<1,1024,0,s1>>>(p_cnt2, p_off2, p_cur2, GI_N);
  k_scatter<<<CDIV(NNZ_GI,256),256,0,s1>>>(gi_rows, gi_cols, gi_vals, NNZ_GI, p_cur2, p_scol2, p_sval2);
  cudaEventRecord(ev_gicsr, s1);
  k_copy2<<<CDIV(GI_N*D,256),256,0,s1>>>(group_emb, G_N*D, item_emb, I_N*D, p_cat);
  k_spmm<<<CDIV(G_N,8),256,0,s1>>>(p_off2, p_scol2, p_sval2, p_cat, p_l1, G_N);
  cudaEventRecord(ev_l1, s1);

  // ---- segment A2 (s0): UI CSR + propagation ----
  k_scatter<<<CDIV(NNZ_UI,256),256>>>(ui_rows, ui_cols, ui_vals, NNZ_UI, p_cur, p_scol, p_sval);
  k_spmm<<<CDIV(UI_N,8),256>>>(p_off, p_scol, p_sval, p_ui0, p_ui1, UI_N);
  k_spmm<<<CDIV(UI_N,8),256>>>(p_off, p_scol, p_sval, p_ui1, p_ui2, UI_N);
  k_spmm<<<CDIV(UI_N,8),256>>>(p_off, p_scol, p_sval, p_ui2, p_ui3, UI_N);
  k_mean_ui<<<CDIV(UI_N*D,256),256>>>();
  cudaEventRecord(ev_A, 0);

  // ---- segment C (s1): user social GEMMs + group pooling ----
  cudaStreamWaitEvent(s1, ev_A, 0);
  k_gemm<<<gemm_u,256,SMEM_MMA,s1>>>(ov_user, p_uemean, p_parts, PSU, U_N, U_N);
  k_red<<<CDIV(U_N*D,256),256,0,s1>>>(p_t1, nullptr, nullptr, p_parts, PSU, U_N*D, KSU);
  k_gemm<<<gemm_u,256,SMEM_MMA,s1>>>(ov_user, p_t1, p_parts, PSU, U_N, U_N);
  k_red<<<CDIV(U_N*D,256),256,0,s1>>>(p_accu, p_uemean, p_t1, p_parts, PSU, U_N*D, KSU);
  k_gul<<<CDIV(G_N,8),256,0,s1>>>(agu, agm);

  // ---- segment D (s0): group-item propagation (overlaps C) ----
  k_copy2<<<CDIV(GI_N*D,256),256>>>(group_emb, G_N*D, p_iemean, I_N*D, p_gi0);
  cudaStreamWaitEvent(0, ev_gicsr, 0);
  k_spmm<<<CDIV(GI_N,8),256>>>(p_off2, p_scol2, p_sval2, p_gi0, p_gi1, GI_N);
  k_spmm<<<CDIV(GI_N,8),256>>>(p_off2, p_scol2, p_sval2, p_gi1, p_gi2, GI_N);
  k_spmm<<<CDIV(GI_N,8),256>>>(p_off2, p_scol2, p_sval2, p_gi2, p_gi3, GI_N);
  k_copy2<<<CDIV(GI_N*D,256),256>>>(group_emb, G_N*D, p_ui2 + U_N*D, I_N*D, p_cat2);
  k_spmm<<<CDIV(G_N,8),256>>>(p_off2, p_scol2, p_sval2, p_cat2, p_l3, G_N);
  cudaStreamWaitEvent(0, ev_l1, 0);
  k_mean_gi<<<CDIV(I_N*D,256),256>>>();
  cudaEventRecord(ev_mg, 0);

  // ---- segment E (s0): item social GEMMs ----
  k_gemm<<<gemm_i,256,SMEM_MMA>>>(ov_item, p_iemb, p_parts2, PSI, I_N, I_N);
  k_red<<<CDIV(I_N*D,256),256>>>(p_it1, nullptr, nullptr, p_parts2, PSI, I_N*D, KSI);
  k_gemm<<<gemm_i,256,SMEM_MMA>>>(ov_item, p_it1, p_parts2, PSI, I_N, I_N);
  k_red<<<CDIV(I_N*D,256),256>>>(p_iacc, p_iemb, p_it1, p_parts2, PSI, I_N*D, KSI);

  // ---- segment F (s1): gate ----
  cudaStreamWaitEvent(s1, ev_mg, 0);
  k_gate<<<CDIV(2*G_N,8),256,0,s1>>>(gate_w1, gate_b1, gate_w2, gate_b2);
  k_gfin<<<CDIV(G_N*D,256),256,0,s1>>>();
  cudaEventRecord(ev_C2, s1);

  // ---- segment G (s0): predict ----
  cudaStreamWaitEvent(0, ev_C2, 0);
  k_pred<<<CDIV(B_N,8),256>>>(gin, iin, pred_w1, pred_b1, pred_w2, pred_b2, out);
}

// round 11
// speedup vs baseline: 2.7643x; 1.1592x over previous
#include <cuda_runtime.h>
#include <cuda_bf16.h>
#include <cstdint>

#define U_N 10000
#define G_N 3000
#define I_N 8000
#define D 32
#define LMEM 20
#define B_N 4096
#define NNZ_UI 720000
#define NNZ_GI 440000
#define UI_N (U_N + I_N)
#define GI_N (G_N + I_N)
#define KSU 5
#define KSI 7
#define TILEM 128
#define TILEK 32
#define ASTR 40                         /* bf16 row stride (80 B) */
#define CDIV(a,b) (((a)+(b)-1)/(b))

/* per-buffer smem layout (bytes) */
#define SZ_A (TILEM*ASTR*2)             /* 10240 */
#define SZ_X (32*ASTR*2)                /* 2560 */
#define OFF_AL SZ_A                     /* 10240 */
#define OFF_XH (2*SZ_A)                 /* 20480 */
#define OFF_XL (2*SZ_A + SZ_X)          /* 23040 */
#define BUFSZ  (2*SZ_A + 2*SZ_X)        /* 25600 */
#define SMEM_MMA (2*BUFSZ)              /* 51200 */

// ----------------- scratch -----------------
__device__ float d_ui0[UI_N*D], d_ui1[UI_N*D], d_ui2[UI_N*D], d_ui3[UI_N*D];
__device__ float d_gi0[GI_N*D], d_gi1[GI_N*D], d_gi2[GI_N*D], d_gi3[GI_N*D];
__device__ float d_cat[GI_N*D], d_cat2[GI_N*D];
__device__ float d_l1[G_N*D], d_l3[G_N*D];
__device__ int   d_cnt[UI_N];
__device__ int   d_off[UI_N+1];
__device__ int   d_cur[UI_N];
__device__ int   d_scol[NNZ_UI];
__device__ float d_sval[NNZ_UI];
__device__ int   d_cnt2[GI_N];
__device__ int   d_off2[GI_N+1];
__device__ int   d_cur2[GI_N];
__device__ int   d_scol2[NNZ_GI];
__device__ float d_sval2[NNZ_GI];

__device__ float d_uemean[U_N*D], d_iemean[I_N*D];
__device__ float d_iemb[I_N*D], d_gemb[G_N*D];
__device__ float d_parts[KSU*U_N*D];
__device__ float d_parts2[KSI*I_N*D];
__device__ float d_t1[U_N*D], d_accu[U_N*D];
__device__ float d_gul[G_N*D];
__device__ float d_wgt[2*G_N];
__device__ float d_gfin[G_N*D];
__device__ float d_it1[I_N*D], d_iacc[I_N*D];

// ----------------- helpers -----------------
__device__ __forceinline__ void split2(float a, float b, uint32_t& h, uint32_t& l) {
  __nv_bfloat162 hb = __floats2bfloat162_rn(a, b);
  float ha = __bfloat162float(hb.x), hc = __bfloat162float(hb.y);
  __nv_bfloat162 lb = __floats2bfloat162_rn(a - ha, b - hc);
  h = *(uint32_t*)&hb; l = *(uint32_t*)&lb;
}

#define MMA16816(c, a, b0v, b1v) \
  asm volatile("mma.sync.aligned.m16n8k16.row.col.f32.bf16.bf16.f32 " \
    "{%0,%1,%2,%3}, {%4,%5,%6,%7}, {%8,%9}, {%0,%1,%2,%3};" \
    : "+f"((c)[0]), "+f"((c)[1]), "+f"((c)[2]), "+f"((c)[3]) \
    : "r"((a)[0]), "r"((a)[1]), "r"((a)[2]), "r"((a)[3]), "r"(b0v), "r"(b1v))

// ----------------- small kernels -----------------
__global__ void k_copy2(const float* __restrict__ a, int na,
                        const float* __restrict__ b, int nb, float* __restrict__ dst) {
  int i = blockIdx.x*blockDim.x + threadIdx.x;
  if (i < na) dst[i] = a[i];
  else if (i < na+nb) dst[i] = b[i-na];
}

__global__ void k_copy_zero(const float* __restrict__ a, int na,
                            const float* __restrict__ b, int nb,
                            float* __restrict__ dst, int* __restrict__ cnt, int ncnt) {
  int i = blockIdx.x*blockDim.x + threadIdx.x;
  if (i < na) dst[i] = a[i];
  else if (i < na+nb) dst[i] = b[i-na];
  if (i < ncnt) cnt[i] = 0;
}

__global__ void k_zero_i(int* p, int n) {
  int i = blockIdx.x*blockDim.x + threadIdx.x;
  if (i < n) p[i] = 0;
}

__global__ void k_count(const int* __restrict__ rows, int nnz, int* cnt) {
  int i = blockIdx.x*blockDim.x + threadIdx.x;
  if (i < nnz) atomicAdd(&cnt[rows[i]], 1);
}

__global__ void __launch_bounds__(1024)
k_scan(const int* __restrict__ cnt, int* __restrict__ off,
       int* __restrict__ cur, int n) {
  __shared__ int warptot[32];
  int t = threadIdx.x;
  int lane = t & 31, w = t >> 5;
  int per = (n + 1023) / 1024;
  int beg = t * per, end = min(n, beg + per);
  int s = 0;
  for (int i = beg; i < end; ++i) s += cnt[i];
  int v = s;
  #pragma unroll
  for (int o = 1; o < 32; o <<= 1) {
    int u = __shfl_up_sync(0xffffffffu, v, o);
    if (lane >= o) v += u;
  }
  if (lane == 31) warptot[w] = v;
  __syncthreads();
  if (w == 0) {
    int x = warptot[lane];
    #pragma unroll
    for (int o = 1; o < 32; o <<= 1) {
      int u = __shfl_up_sync(0xffffffffu, x, o);
      if (lane >= o) x += u;
    }
    warptot[lane] = x;
  }
  __syncthreads();
  int run = (w ? warptot[w-1] : 0) + v - s;
  for (int i = beg; i < end; ++i) {
    int c = cnt[i];
    off[i] = run; cur[i] = run;
    run += c;
  }
  if (t == 0) off[n] = warptot[31];
}

__global__ void k_scatter(const int* __restrict__ rows, const int* __restrict__ cols,
                          const float* __restrict__ vals, int nnz,
                          int* cur, int* __restrict__ scol, float* __restrict__ sval) {
  int i = blockIdx.x*blockDim.x + threadIdx.x;
  if (i < nnz) {
    int r = rows[i];
    int p = atomicAdd(&cur[r], 1);
    scol[p] = cols[i];
    sval[p] = vals[i];
  }
}

__global__ void k_spmm(const int* __restrict__ off, const int* __restrict__ scol,
                       const float* __restrict__ sval, const float* __restrict__ x,
                       float* __restrict__ y, int nrows) {
  int row = blockIdx.x*8 + (threadIdx.x >> 5);
  int lane = threadIdx.x & 31;
  if (row >= nrows) return;
  int s = off[row], e = off[row+1];
  float acc = 0.f;
  int p = s;
  for (; p + 4 <= e; p += 4) {
    int c0 = __ldg(&scol[p]),   c1 = __ldg(&scol[p+1]);
    int c2 = __ldg(&scol[p+2]), c3 = __ldg(&scol[p+3]);
    float v0 = __ldg(&sval[p]),   v1 = __ldg(&sval[p+1]);
    float v2 = __ldg(&sval[p+2]), v3 = __ldg(&sval[p+3]);
    float x0 = x[c0*D + lane], x1 = x[c1*D + lane];
    float x2 = x[c2*D + lane], x3 = x[c3*D + lane];
    acc = fmaf(v0, x0, acc); acc = fmaf(v1, x1, acc);
    acc = fmaf(v2, x2, acc); acc = fmaf(v3, x3, acc);
  }
  for (; p < e; ++p)
    acc = fmaf(__ldg(&sval[p]), x[__ldg(&scol[p])*D + lane], acc);
  y[row*D + lane] = acc;
}

__global__ void k_mean_ui() {
  int i = blockIdx.x*blockDim.x + threadIdx.x;
  if (i >= UI_N*D) return;
  float m = 0.25f*(d_ui0[i] + d_ui1[i] + d_ui2[i] + d_ui3[i]);
  if (i < U_N*D) d_uemean[i] = m;
  else d_iemean[i - U_N*D] = m;
}

__global__ void k_mean_gi() {
  int i = blockIdx.x*blockDim.x + threadIdx.x;
  if (i < G_N*D)
    d_gemb[i] = 0.25f*(d_gi0[i] + d_l1[i] + d_gi2[i] + d_l3[i]);
  if (i < I_N*D) {
    int j = G_N*D + i;
    d_iemb[i] = 0.25f*(d_gi0[j] + d_gi1[j] + d_gi2[j] + d_gi3[j]);
  }
}

// ---------- bf16 mma.sync GEMM: Parts[y][N,32] = A[N,kslice] @ X[kslice,32] ----------
// hi/lo split: D += Ah*Xh + Al*Xh + Ah*Xl. 256 thr, 128-row tile, 32-k chunks,
// DOUBLE-buffered smem (ldg -> compute -> sts-other-buf -> 1 sync). 3 CTAs/SM.
extern "C" __global__ void __launch_bounds__(256, 3)
k_gemm(const float* __restrict__ A, const float* __restrict__ X,
       float* __restrict__ Pbase, size_t pstride, int N, int K) {
  extern __shared__ char smem[];
  const int tid = threadIdx.x;
  const int w = tid >> 5, lane = tid & 31;
  const int rowbase = blockIdx.x * TILEM;
  const int ks = gridDim.y;
  const int kchunk = CDIV(CDIV(K, ks), TILEK) * TILEK;
  const int kbeg = blockIdx.y * kchunk;
  const int kend = min(K, kbeg + kchunk);
  const int nch = (kend > kbeg) ? CDIV(kend - kbeg, TILEK) : 0;

  // staging: A = 1 row-half (16 k) per thread; X = 4 floats per thread
  const int arow = tid >> 1;            // 0..127
  const int ahalf = tid & 1;            // k offset 16*ahalf
  const int xn = tid & 31;              // X col 0..31
  const int xw = tid >> 5;              // X k group: xw*4..+3

  float av[16];
  float xv[4];
  float acc[4][4];
  #pragma unroll
  for (int t = 0; t < 4; ++t)
    #pragma unroll
    for (int j = 0; j < 4; ++j) acc[t][j] = 0.f;

  auto ldAB = [&](int k0) {
    int gr = rowbase + arow;
    int kk = k0 + 16*ahalf;
    if (gr < N) {
      #pragma unroll
      for (int c = 0; c < 4; ++c) {
        int k = kk + 4*c;
        if (k + 4 <= kend) {
          float4 v = *(const float4*)(A + (size_t)gr*K + k);
          av[4*c] = v.x; av[4*c+1] = v.y; av[4*c+2] = v.z; av[4*c+3] = v.w;
        } else {
          #pragma unroll
          for (int j = 0; j < 4; ++j)
            av[4*c+j] = (k + j < kend) ? A[(size_t)gr*K + k + j] : 0.f;
        }
      }
    } else {
      #pragma unroll
      for (int j = 0; j < 16; ++j) av[j] = 0.f;
    }
    #pragma unroll
    for (int j = 0; j < 4; ++j) {
      int k = k0 + xw*4 + j;
      xv[j] = (k < kend) ? X[(size_t)k*D + xn] : 0.f;
    }
  };

  auto stAB = [&](int b) {
    char* B = smem + b*BUFSZ;
    #pragma unroll
    for (int j = 0; j < 8; ++j) {
      uint32_t h, l;
      split2(av[2*j], av[2*j+1], h, l);
      uint32_t off = (uint32_t)(arow*ASTR + 16*ahalf + 2*j) * 2;
      *(uint32_t*)(B + off) = h;
      *(uint32_t*)(B + OFF_AL + off) = l;
    }
    #pragma unroll
    for (int j = 0; j < 2; ++j) {
      uint32_t h, l;
      split2(xv[2*j], xv[2*j+1], h, l);
      uint32_t off = (uint32_t)(xn*ASTR + xw*4 + 2*j) * 2;
      *(uint32_t*)(B + OFF_XH + off) = h;
      *(uint32_t*)(B + OFF_XL + off) = l;
    }
  };

  if (nch > 0) {
    ldAB(kbeg);
    stAB(0);
    __syncthreads();
    for (int i = 0; i < nch; ++i) {
      int b = i & 1;
      if (i + 1 < nch) ldAB(kbeg + (i+1)*TILEK);   // LDG hides under compute

      char* B = smem + b*BUFSZ;
      #pragma unroll
      for (int s = 0; s < 2; ++s) {
        int r0 = w*16 + (lane >> 2);
        int kc = 16*s + 2*(lane & 3);
        uint32_t oa = (uint32_t)(r0*ASTR + kc)*2;
        uint32_t ah[4], al[4];
        ah[0] = *(uint32_t*)(B + oa);
        ah[1] = *(uint32_t*)(B + oa + 8*ASTR*2);
        ah[2] = *(uint32_t*)(B + oa + 16);
        ah[3] = *(uint32_t*)(B + oa + 8*ASTR*2 + 16);
        al[0] = *(uint32_t*)(B + OFF_AL + oa);
        al[1] = *(uint32_t*)(B + OFF_AL + oa + 8*ASTR*2);
        al[2] = *(uint32_t*)(B + OFF_AL + oa + 16);
        al[3] = *(uint32_t*)(B + OFF_AL + oa + 8*ASTR*2 + 16);
        #pragma unroll
        for (int t = 0; t < 4; ++t) {
          int n0 = t*8 + (lane >> 2);
          uint32_t ob = (uint32_t)(n0*ASTR + kc)*2;
          uint32_t bh0 = *(uint32_t*)(B + OFF_XH + ob);
          uint32_t bh1 = *(uint32_t*)(B + OFF_XH + ob + 16);
          uint32_t bl0 = *(uint32_t*)(B + OFF_XL + ob);
          uint32_t bl1 = *(uint32_t*)(B + OFF_XL + ob + 16);
          MMA16816(acc[t], ah, bh0, bh1);
          MMA16816(acc[t], al, bh0, bh1);
          MMA16816(acc[t], ah, bl0, bl1);
        }
      }
      if (i + 1 < nch) stAB(b ^ 1);                // STS into other buffer
      __syncthreads();
    }
  }

  // epilogue: c0,c1 -> (row, col..col+1); c2,c3 -> (row+8, ...)
  float* P = Pbase + (size_t)blockIdx.y * pstride;
  int rr = rowbase + w*16 + (lane >> 2);
  int cc = (lane & 3)*2;
  #pragma unroll
  for (int t = 0; t < 4; ++t) {
    if (rr < N)
      *(float2*)(P + (size_t)rr*D + t*8 + cc) = make_float2(acc[t][0], acc[t][1]);
    if (rr + 8 < N)
      *(float2*)(P + (size_t)(rr+8)*D + t*8 + cc) = make_float2(acc[t][2], acc[t][3]);
  }
}

__global__ void k_red(float* __restrict__ dst, const float* __restrict__ b0,
                      const float* __restrict__ b1, const float* __restrict__ parts,
                      size_t pstride, int n, int ks) {
  int i = blockIdx.x*blockDim.x + threadIdx.x;
  if (i >= n) return;
  float s = 0.f;
  for (int p = 0; p < ks; ++p) s += parts[(size_t)p*pstride + i];
  if (b0) s += b0[i];
  if (b1) s += b1[i];
  dst[i] = s;
}

__global__ void k_gul(const int* __restrict__ gu, const float* __restrict__ gm) {
  int g = blockIdx.x*8 + (threadIdx.x >> 5);
  int lane = threadIdx.x & 31;
  if (g >= G_N) return;
  float acc = 0.f;
  #pragma unroll
  for (int l = 0; l < LMEM; ++l) {
    int u = __ldg(&gu[g*LMEM + l]);
    float m = __ldg(&gm[g*LMEM + l]);
    acc = fmaf(m, d_accu[u*D + lane], acc);
  }
  d_gul[g*D + lane] = acc;
}

__global__ void k_gate(const float* __restrict__ w1, const float* __restrict__ b1,
                       const float* __restrict__ w2, const float* __restrict__ b2) {
  int row = blockIdx.x*8 + (threadIdx.x >> 5);
  int lane = threadIdx.x & 31;
  if (row >= 2*G_N) return;
  const float* x = (row < G_N) ? &d_gemb[row*D] : &d_gul[(row - G_N)*D];
  float xv = x[lane];
  float h = b1[lane];
  #pragma unroll
  for (int k = 0; k < 32; ++k) {
    float xk = __shfl_sync(0xffffffffu, xv, k);
    h = fmaf(xk, w1[k*D + lane], h);
  }
  h = fmaxf(h, 0.f);
  float s = h * w2[lane];
  #pragma unroll
  for (int o = 16; o > 0; o >>= 1) s += __shfl_xor_sync(0xffffffffu, s, o);
  if (lane == 0) d_wgt[row] = 1.f/(1.f + expf(-(s + b2[0])));
}

__global__ void k_gfin() {
  int i = blockIdx.x*blockDim.x + threadIdx.x;
  if (i >= G_N*D) return;
  int g = i / D;
  d_gfin[i] = d_wgt[g]*d_gemb[i] + d_wgt[G_N + g]*d_gul[i];
}

__global__ void k_pred(const int* __restrict__ gin, const int* __restrict__ iin,
                       const float* __restrict__ w1, const float* __restrict__ b1,
                       const float* __restrict__ w2, const float* __restrict__ b2,
                       float* __restrict__ out) {
  int b = blockIdx.x*8 + (threadIdx.x >> 5);
  int lane = threadIdx.x & 31;
  if (b >= B_N) return;
  float e = d_gfin[gin[b]*D + lane] * d_iacc[iin[b]*D + lane];
  float z = 0.f;
  #pragma unroll
  for (int j = 0; j < 8; ++j) {
    float v = e * w1[lane*8 + j];
    #pragma unroll
    for (int o = 16; o > 0; o >>= 1) v += __shfl_xor_sync(0xffffffffu, v, o);
    if (lane == 0) z += fmaxf(v + b1[j], 0.f) * w2[j];
  }
  if (lane == 0) out[b] = 1.f/(1.f + expf(-(z + b2[0])));
}

// ----------------- host -----------------
template <typename T>
static T* symaddr(const void* sym) {
  void* p = nullptr;
  cudaGetSymbolAddress(&p, sym);
  return (T*)p;
}

extern "C" void kernel_launch(void* const* d_in, const int* in_sizes, int n_in,
                              void* d_out, int out_size) {
  const int*   gin       = (const int*)d_in[0];
  const int*   iin       = (const int*)d_in[1];
  const float* user_emb  = (const float*)d_in[2];
  const float* group_emb = (const float*)d_in[3];
  const float* item_emb  = (const float*)d_in[4];
  const int*   ui_rows   = (const int*)d_in[5];
  const int*   ui_cols   = (const int*)d_in[6];
  const float* ui_vals   = (const float*)d_in[7];
  const int*   gi_rows   = (const int*)d_in[8];
  const int*   gi_cols   = (const int*)d_in[9];
  const float* gi_vals   = (const float*)d_in[10];
  const float* ov_user   = (const float*)d_in[11];
  const float* ov_item   = (const float*)d_in[12];
  const int*   agu       = (const int*)d_in[13];
  const float* agm       = (const float*)d_in[14];
  const float* gate_w1   = (const float*)d_in[15];
  const float* gate_b1   = (const float*)d_in[16];
  const float* gate_w2   = (const float*)d_in[17];
  const float* gate_b2   = (const float*)d_in[18];
  const float* pred_w1   = (const float*)d_in[19];
  const float* pred_b1   = (const float*)d_in[20];
  const float* pred_w2   = (const float*)d_in[21];
  const float* pred_b2   = (const float*)d_in[22];
  float* out = (float*)d_out;

  cudaFuncSetAttribute(k_gemm, cudaFuncAttributeMaxDynamicSharedMemorySize, SMEM_MMA);

  float *p_ui0 = symaddr<float>(d_ui0), *p_ui1 = symaddr<float>(d_ui1);
  float *p_ui2 = symaddr<float>(d_ui2), *p_ui3 = symaddr<float>(d_ui3);
  float *p_gi0 = symaddr<float>(d_gi0), *p_gi1 = symaddr<float>(d_gi1);
  float *p_gi2 = symaddr<float>(d_gi2), *p_gi3 = symaddr<float>(d_gi3);
  float *p_cat  = symaddr<float>(d_cat), *p_cat2 = symaddr<float>(d_cat2);
  float *p_l1  = symaddr<float>(d_l1),  *p_l3  = symaddr<float>(d_l3);
  int *p_cnt  = symaddr<int>(d_cnt),  *p_off  = symaddr<int>(d_off),  *p_cur  = symaddr<int>(d_cur);
  int *p_cnt2 = symaddr<int>(d_cnt2), *p_off2 = symaddr<int>(d_off2), *p_cur2 = symaddr<int>(d_cur2);
  int *p_scol = symaddr<int>(d_scol), *p_scol2 = symaddr<int>(d_scol2);
  float *p_sval = symaddr<float>(d_sval), *p_sval2 = symaddr<float>(d_sval2);
  float *p_uemean = symaddr<float>(d_uemean), *p_iemean = symaddr<float>(d_iemean);
  float *p_iemb = symaddr<float>(d_iemb);
  float *p_parts = symaddr<float>(d_parts), *p_parts2 = symaddr<float>(d_parts2);
  float *p_t1 = symaddr<float>(d_t1), *p_accu = symaddr<float>(d_accu);
  float *p_it1 = symaddr<float>(d_it1), *p_iacc = symaddr<float>(d_iacc);

  const size_t PSU = (size_t)U_N * D;
  const size_t PSI = (size_t)I_N * D;
  dim3 gemm_u(CDIV(U_N, TILEM), KSU);
  dim3 gemm_i(CDIV(I_N, TILEM), KSI);

  cudaStream_t s1;
  cudaStreamCreateWithFlags(&s1, cudaStreamNonBlocking);
  cudaEvent_t ev_fork, ev_gicsr, ev_l1, ev_A, ev_mg, ev_C2;
  cudaEventCreateWithFlags(&ev_fork,  cudaEventDisableTiming);
  cudaEventCreateWithFlags(&ev_gicsr, cudaEventDisableTiming);
  cudaEventCreateWithFlags(&ev_l1,    cudaEventDisableTiming);
  cudaEventCreateWithFlags(&ev_A,     cudaEventDisableTiming);
  cudaEventCreateWithFlags(&ev_mg,    cudaEventDisableTiming);
  cudaEventCreateWithFlags(&ev_C2,    cudaEventDisableTiming);

  cudaEventRecord(ev_fork, 0);

  // ---- segment A1 (s0): launches #1..#4; #4 = representative GEMM for ncu ----
  k_copy_zero<<<CDIV((U_N+I_N)*D,256),256>>>(user_emb, U_N*D, item_emb, I_N*D, p_ui0, p_cnt, UI_N);
  k_count<<<CDIV(NNZ_UI,256),256>>>(ui_rows, NNZ_UI, p_cnt);
  k_scan<<<1,1024>>>(p_cnt, p_off, p_cur, UI_N);
  // HOOK (launch #4): steady-state MMA GEMM on ov_user, truncated K; output overwritten later.
  k_gemm<<<gemm_u,256,SMEM_MMA>>>(ov_user, ov_user, p_parts, PSU, U_N, 1536);

  // ---- segment B (s1): GI CSR build + l1 ----
  cudaStreamWaitEvent(s1, ev_fork, 0);
  k_zero_i<<<CDIV(GI_N,256),256,0,s1>>>(p_cnt2, GI_N);
  k_count<<<CDIV(NNZ_GI,256),256,0,s1>>>(gi_rows, NNZ_GI, p_cnt2);
  k_scan<<<1,1024,0,s1>>>(p_cnt2, p_off2, p_cur2, GI_N);
  k_scatter<<<CDIV(NNZ_GI,256),256,0,s1>>>(gi_rows, gi_cols, gi_vals, NNZ_GI, p_cur2, p_scol2, p_sval2);
  cudaEventRecord(ev_gicsr, s1);
  k_copy2<<<CDIV(GI_N*D,256),256,0,s1>>>(group_emb, G_N*D, item_emb, I_N*D, p_cat);
  k_spmm<<<CDIV(G_N,8),256,0,s1>>>(p_off2, p_scol2, p_sval2, p_cat, p_l1, G_N);
  cudaEventRecord(ev_l1, s1);

  // ---- segment A2 (s0): UI CSR + propagation ----
  k_scatter<<<CDIV(NNZ_UI,256),256>>>(ui_rows, ui_cols, ui_vals, NNZ_UI, p_cur, p_scol, p_sval);
  k_spmm<<<CDIV(UI_N,8),256>>>(p_off, p_scol, p_sval, p_ui0, p_ui1, UI_N);
  k_spmm<<<CDIV(UI_N,8),256>>>(p_off, p_scol, p_sval, p_ui1, p_ui2, UI_N);
  k_spmm<<<CDIV(UI_N,8),256>>>(p_off, p_scol, p_sval, p_ui2, p_ui3, UI_N);
  k_mean_ui<<<CDIV(UI_N*D,256),256>>>();
  cudaEventRecord(ev_A, 0);

  // ---- segment C (s1): user social GEMMs + group pooling ----
  cudaStreamWaitEvent(s1, ev_A, 0);
  k_gemm<<<gemm_u,256,SMEM_MMA,s1>>>(ov_user, p_uemean, p_parts, PSU, U_N, U_N);
  k_red<<<CDIV(U_N*D,256),256,0,s1>>>(p_t1, nullptr, nullptr, p_parts, PSU, U_N*D, KSU);
  k_gemm<<<gemm_u,256,SMEM_MMA,s1>>>(ov_user, p_t1, p_parts, PSU, U_N, U_N);
  k_red<<<CDIV(U_N*D,256),256,0,s1>>>(p_accu, p_uemean, p_t1, p_parts, PSU, U_N*D, KSU);
  k_gul<<<CDIV(G_N,8),256,0,s1>>>(agu, agm);

  // ---- segment D (s0): group-item propagation (overlaps C) ----
  k_copy2<<<CDIV(GI_N*D,256),256>>>(group_emb, G_N*D, p_iemean, I_N*D, p_gi0);
  cudaStreamWaitEvent(0, ev_gicsr, 0);
  k_spmm<<<CDIV(GI_N,8),256>>>(p_off2, p_scol2, p_sval2, p_gi0, p_gi1, GI_N);
  k_spmm<<<CDIV(GI_N,8),256>>>(p_off2, p_scol2, p_sval2, p_gi1, p_gi2, GI_N);
  k_spmm<<<CDIV(GI_N,8),256>>>(p_off2, p_scol2, p_sval2, p_gi2, p_gi3, GI_N);
  k_copy2<<<CDIV(GI_N*D,256),256>>>(group_emb, G_N*D, p_ui2 + U_N*D, I_N*D, p_cat2);
  k_spmm<<<CDIV(G_N,8),256>>>(p_off2, p_scol2, p_sval2, p_cat2, p_l3, G_N);
  cudaStreamWaitEvent(0, ev_l1, 0);
  k_mean_gi<<<CDIV(I_N*D,256),256>>>();
  cudaEventRecord(ev_mg, 0);

  // ---- segment E (s0): item social GEMMs ----
  k_gemm<<<gemm_i,256,SMEM_MMA>>>(ov_item, p_iemb, p_parts2, PSI, I_N, I_N);
  k_red<<<CDIV(I_N*D,256),256>>>(p_it1, nullptr, nullptr, p_parts2, PSI, I_N*D, KSI);
  k_gemm<<<gemm_i,256,SMEM_MMA>>>(ov_item, p_it1, p_parts2, PSI, I_N, I_N);
  k_red<<<CDIV(I_N*D,256),256>>>(p_iacc, p_iemb, p_it1, p_parts2, PSI, I_N*D, KSI);

  // ---- segment F (s1): gate ----
  cudaStreamWaitEvent(s1, ev_mg, 0);
  k_gate<<<CDIV(2*G_N,8),256,0,s1>>>(gate_w1, gate_b1, gate_w2, gate_b2);
  k_gfin<<<CDIV(G_N*D,256),256,0,s1>>>();
  cudaEventRecord(ev_C2, s1);

  // ---- segment G (s0): predict ----
  cudaStreamWaitEvent(0, ev_C2, 0);
  k_pred<<<CDIV(B_N,8),256>>>(gin, iin, pred_w1, pred_b1, pred_w2, pred_b2, out);
}

// round 12
// speedup vs baseline: 3.6165x; 1.3083x over previous
#include <cuda_runtime.h>
#include <cuda_bf16.h>
#include <cstdint>

#define U_N 10000
#define G_N 3000
#define I_N 8000
#define D 32
#define LMEM 20
#define B_N 4096
#define NNZ_UI 720000
#define NNZ_GI 440000
#define UI_N (U_N + I_N)
#define GI_N (G_N + I_N)
#define KSU 5
#define KSI 7
#define TILEM 128
#define TILEK 32
#define XSTR 40                         /* bf16 stride per n-row */
#define CDIV(a,b) (((a)+(b)-1)/(b))

/* smem: X only, double-buffered, hi+lo */
#define SZ_X (32*XSTR*2)                /* 2560 B per matrix */
#define BUFSZ (2*SZ_X)                  /* hi + lo = 5120 */
#define SMEM_MMA (2*BUFSZ)              /* 10240 */

// ----------------- scratch -----------------
__device__ float d_ui0[UI_N*D], d_ui1[UI_N*D], d_ui2[UI_N*D], d_ui3[UI_N*D];
__device__ float d_gi0[GI_N*D], d_gi1[GI_N*D], d_gi2[GI_N*D], d_gi3[GI_N*D];
__device__ float d_cat[GI_N*D], d_cat2[GI_N*D];
__device__ float d_l1[G_N*D], d_l3[G_N*D];
__device__ int   d_cnt[UI_N];
__device__ int   d_off[UI_N+1];
__device__ int   d_cur[UI_N];
__device__ int   d_scol[NNZ_UI];
__device__ float d_sval[NNZ_UI];
__device__ int   d_cnt2[GI_N];
__device__ int   d_off2[GI_N+1];
__device__ int   d_cur2[GI_N];
__device__ int   d_scol2[NNZ_GI];
__device__ float d_sval2[NNZ_GI];

__device__ float d_uemean[U_N*D], d_iemean[I_N*D];
__device__ float d_iemb[I_N*D], d_gemb[G_N*D];
__device__ float d_parts[KSU*U_N*D];
__device__ float d_parts2[KSI*I_N*D];
__device__ float d_t1[U_N*D], d_accu[U_N*D];
__device__ float d_gul[G_N*D];
__device__ float d_wgt[2*G_N];
__device__ float d_gfin[G_N*D];
__device__ float d_it1[I_N*D], d_iacc[I_N*D];

// ----------------- helpers -----------------
__device__ __forceinline__ void split2(float a, float b, uint32_t& h, uint32_t& l) {
  __nv_bfloat162 hb = __floats2bfloat162_rn(a, b);
  float ha = __bfloat162float(hb.x), hc = __bfloat162float(hb.y);
  __nv_bfloat162 lb = __floats2bfloat162_rn(a - ha, b - hc);
  h = *(uint32_t*)&hb; l = *(uint32_t*)&lb;
}

#define MMA16816(c, a, b0v, b1v) \
  asm volatile("mma.sync.aligned.m16n8k16.row.col.f32.bf16.bf16.f32 " \
    "{%0,%1,%2,%3}, {%4,%5,%6,%7}, {%8,%9}, {%0,%1,%2,%3};" \
    : "+f"((c)[0]), "+f"((c)[1]), "+f"((c)[2]), "+f"((c)[3]) \
    : "r"((a)[0]), "r"((a)[1]), "r"((a)[2]), "r"((a)[3]), "r"(b0v), "r"(b1v))

// ----------------- small kernels -----------------
__global__ void k_copy2(const float* __restrict__ a, int na,
                        const float* __restrict__ b, int nb, float* __restrict__ dst) {
  int i = blockIdx.x*blockDim.x + threadIdx.x;
  if (i < na) dst[i] = a[i];
  else if (i < na+nb) dst[i] = b[i-na];
}

__global__ void k_copy_zero(const float* __restrict__ a, int na,
                            const float* __restrict__ b, int nb,
                            float* __restrict__ dst, int* __restrict__ cnt, int ncnt) {
  int i = blockIdx.x*blockDim.x + threadIdx.x;
  if (i < na) dst[i] = a[i];
  else if (i < na+nb) dst[i] = b[i-na];
  if (i < ncnt) cnt[i] = 0;
}

__global__ void k_zero_i(int* p, int n) {
  int i = blockIdx.x*blockDim.x + threadIdx.x;
  if (i < n) p[i] = 0;
}

__global__ void k_count(const int* __restrict__ rows, int nnz, int* cnt) {
  int i = blockIdx.x*blockDim.x + threadIdx.x;
  if (i < nnz) atomicAdd(&cnt[rows[i]], 1);
}

__global__ void __launch_bounds__(1024)
k_scan(const int* __restrict__ cnt, int* __restrict__ off,
       int* __restrict__ cur, int n) {
  __shared__ int warptot[32];
  int t = threadIdx.x;
  int lane = t & 31, w = t >> 5;
  int per = (n + 1023) / 1024;
  int beg = t * per, end = min(n, beg + per);
  int s = 0;
  for (int i = beg; i < end; ++i) s += cnt[i];
  int v = s;
  #pragma unroll
  for (int o = 1; o < 32; o <<= 1) {
    int u = __shfl_up_sync(0xffffffffu, v, o);
    if (lane >= o) v += u;
  }
  if (lane == 31) warptot[w] = v;
  __syncthreads();
  if (w == 0) {
    int x = warptot[lane];
    #pragma unroll
    for (int o = 1; o < 32; o <<= 1) {
      int u = __shfl_up_sync(0xffffffffu, x, o);
      if (lane >= o) x += u;
    }
    warptot[lane] = x;
  }
  __syncthreads();
  int run = (w ? warptot[w-1] : 0) + v - s;
  for (int i = beg; i < end; ++i) {
    int c = cnt[i];
    off[i] = run; cur[i] = run;
    run += c;
  }
  if (t == 0) off[n] = warptot[31];
}

__global__ void k_scatter(const int* __restrict__ rows, const int* __restrict__ cols,
                          const float* __restrict__ vals, int nnz,
                          int* cur, int* __restrict__ scol, float* __restrict__ sval) {
  int i = blockIdx.x*blockDim.x + threadIdx.x;
  if (i < nnz) {
    int r = rows[i];
    int p = atomicAdd(&cur[r], 1);
    scol[p] = cols[i];
    sval[p] = vals[i];
  }
}

__global__ void k_spmm(const int* __restrict__ off, const int* __restrict__ scol,
                       const float* __restrict__ sval, const float* __restrict__ x,
                       float* __restrict__ y, int nrows) {
  int row = blockIdx.x*8 + (threadIdx.x >> 5);
  int lane = threadIdx.x & 31;
  if (row >= nrows) return;
  int s = off[row], e = off[row+1];
  float acc = 0.f;
  int p = s;
  for (; p + 4 <= e; p += 4) {
    int c0 = __ldg(&scol[p]),   c1 = __ldg(&scol[p+1]);
    int c2 = __ldg(&scol[p+2]), c3 = __ldg(&scol[p+3]);
    float v0 = __ldg(&sval[p]),   v1 = __ldg(&sval[p+1]);
    float v2 = __ldg(&sval[p+2]), v3 = __ldg(&sval[p+3]);
    float x0 = x[c0*D + lane], x1 = x[c1*D + lane];
    float x2 = x[c2*D + lane], x3 = x[c3*D + lane];
    acc = fmaf(v0, x0, acc); acc = fmaf(v1, x1, acc);
    acc = fmaf(v2, x2, acc); acc = fmaf(v3, x3, acc);
  }
  for (; p < e; ++p)
    acc = fmaf(__ldg(&sval[p]), x[__ldg(&scol[p])*D + lane], acc);
  y[row*D + lane] = acc;
}

__global__ void k_mean_ui() {
  int i = blockIdx.x*blockDim.x + threadIdx.x;
  if (i >= UI_N*D) return;
  float m = 0.25f*(d_ui0[i] + d_ui1[i] + d_ui2[i] + d_ui3[i]);
  if (i < U_N*D) d_uemean[i] = m;
  else d_iemean[i - U_N*D] = m;
}

__global__ void k_mean_gi() {
  int i = blockIdx.x*blockDim.x + threadIdx.x;
  if (i < G_N*D)
    d_gemb[i] = 0.25f*(d_gi0[i] + d_l1[i] + d_gi2[i] + d_l3[i]);
  if (i < I_N*D) {
    int j = G_N*D + i;
    d_iemb[i] = 0.25f*(d_gi0[j] + d_gi1[j] + d_gi2[j] + d_gi3[j]);
  }
}

// ---------- bf16 mma.sync GEMM: Parts[y][N,32] = A[N,kslice] @ X[kslice,32] ----------
// hi/lo split: D += Ah*Xh + Al*Xh + Ah*Xl.
// A: fragment-direct LDG.64 from gmem (coalesced 32B/row), converted in regs — NO A smem.
// X: double-buffered smem (hi+lo bf16), 10 KB total. 256 thr, 128-row tile, 32-k chunks.
extern "C" __global__ void __launch_bounds__(256, 3)
k_gemm(const float* __restrict__ A, const float* __restrict__ X,
       float* __restrict__ Pbase, size_t pstride, int N, int K) {
  extern __shared__ char smem[];
  const int tid = threadIdx.x;
  const int w = tid >> 5, lane = tid & 31;
  const int rowbase = blockIdx.x * TILEM;
  const int ks = gridDim.y;
  const int kchunk = CDIV(CDIV(K, ks), TILEK) * TILEK;
  const int kbeg = blockIdx.y * kchunk;
  const int kend = min(K, kbeg + kchunk);
  const int nch = (kend > kbeg) ? CDIV(kend - kbeg, TILEK) : 0;

  const int r0l = w*16 + (lane >> 2);   // fragment row (local tile row)
  const int kcl = 2*(lane & 3);         // fragment k within 16-group
  const int xn = tid & 31;              // X staging: col
  const int xw = tid >> 5;              // X staging: k group xw*4..+3

  float acc[4][4];
  #pragma unroll
  for (int t = 0; t < 4; ++t)
    #pragma unroll
    for (int j = 0; j < 4; ++j) acc[t][j] = 0.f;

  float aL[16], aN[16];
  float xv[4];

  auto ldA = [&](int k0, float* a) {
    int gr0 = rowbase + r0l;
    #pragma unroll
    for (int s = 0; s < 2; ++s) {
      #pragma unroll
      for (int q = 0; q < 4; ++q) {
        int gr = gr0 + 8*(q & 1);
        int k  = k0 + 16*s + kcl + 8*(q >> 1);
        float2 v = make_float2(0.f, 0.f);
        if (gr < N) {
          if (k + 2 <= kend) v = *(const float2*)(A + (size_t)gr*K + k);
          else if (k < kend) v.x = A[(size_t)gr*K + k];
        }
        a[s*8 + q*2]     = v.x;
        a[s*8 + q*2 + 1] = v.y;
      }
    }
  };
  auto ldX = [&](int k0) {
    #pragma unroll
    for (int j = 0; j < 4; ++j) {
      int k = k0 + xw*4 + j;
      xv[j] = (k < kend) ? X[(size_t)k*D + xn] : 0.f;
    }
  };
  auto stX = [&](int b) {
    char* B = smem + b*BUFSZ;
    #pragma unroll
    for (int j = 0; j < 2; ++j) {
      uint32_t h, l;
      split2(xv[2*j], xv[2*j+1], h, l);
      uint32_t off = (uint32_t)(xn*XSTR + xw*4 + 2*j) * 2;
      *(uint32_t*)(B + off) = h;
      *(uint32_t*)(B + SZ_X + off) = l;
    }
  };

  if (nch > 0) {
    ldX(kbeg);
    ldA(kbeg, aL);
    stX(0);
    __syncthreads();
    for (int i = 0; i < nch; ++i) {
      int b = i & 1;
      if (i + 1 < nch) { ldX(kbeg + (i+1)*TILEK); ldA(kbeg + (i+1)*TILEK, aN); }

      char* BH = smem + b*BUFSZ;
      char* BL = BH + SZ_X;
      #pragma unroll
      for (int s = 0; s < 2; ++s) {
        uint32_t ah[4], al[4];
        #pragma unroll
        for (int q = 0; q < 4; ++q)
          split2(aL[s*8 + 2*q], aL[s*8 + 2*q + 1], ah[q], al[q]);
        #pragma unroll
        for (int t = 0; t < 4; ++t) {
          int n0 = t*8 + (lane >> 2);
          uint32_t ob = (uint32_t)(n0*XSTR + 16*s + kcl) * 2;
          uint32_t bh0 = *(uint32_t*)(BH + ob);
          uint32_t bh1 = *(uint32_t*)(BH + ob + 16);
          uint32_t bl0 = *(uint32_t*)(BL + ob);
          uint32_t bl1 = *(uint32_t*)(BL + ob + 16);
          MMA16816(acc[t], ah, bh0, bh1);
          MMA16816(acc[t], al, bh0, bh1);
          MMA16816(acc[t], ah, bl0, bl1);
        }
      }
      if (i + 1 < nch) stX(b ^ 1);
      __syncthreads();
      #pragma unroll
      for (int j = 0; j < 16; ++j) aL[j] = aN[j];
    }
  }

  // epilogue: c0,c1 -> (row, col..col+1); c2,c3 -> (row+8, ...)
  float* P = Pbase + (size_t)blockIdx.y * pstride;
  int rr = rowbase + r0l;
  int cc = (lane & 3)*2;
  #pragma unroll
  for (int t = 0; t < 4; ++t) {
    if (rr < N)
      *(float2*)(P + (size_t)rr*D + t*8 + cc) = make_float2(acc[t][0], acc[t][1]);
    if (rr + 8 < N)
      *(float2*)(P + (size_t)(rr+8)*D + t*8 + cc) = make_float2(acc[t][2], acc[t][3]);
  }
}

__global__ void k_red(float* __restrict__ dst, const float* __restrict__ b0,
                      const float* __restrict__ b1, const float* __restrict__ parts,
                      size_t pstride, int n, int ks) {
  int i = blockIdx.x*blockDim.x + threadIdx.x;
  if (i >= n) return;
  float s = 0.f;
  for (int p = 0; p < ks; ++p) s += parts[(size_t)p*pstride + i];
  if (b0) s += b0[i];
  if (b1) s += b1[i];
  dst[i] = s;
}

__global__ void k_gul(const int* __restrict__ gu, const float* __restrict__ gm) {
  int g = blockIdx.x*8 + (threadIdx.x >> 5);
  int lane = threadIdx.x & 31;
  if (g >= G_N) return;
  float acc = 0.f;
  #pragma unroll
  for (int l = 0; l < LMEM; ++l) {
    int u = __ldg(&gu[g*LMEM + l]);
    float m = __ldg(&gm[g*LMEM + l]);
    acc = fmaf(m, d_accu[u*D + lane], acc);
  }
  d_gul[g*D + lane] = acc;
}

__global__ void k_gate(const float* __restrict__ w1, const float* __restrict__ b1,
                       const float* __restrict__ w2, const float* __restrict__ b2) {
  int row = blockIdx.x*8 + (threadIdx.x >> 5);
  int lane = threadIdx.x & 31;
  if (row >= 2*G_N) return;
  const float* x = (row < G_N) ? &d_gemb[row*D] : &d_gul[(row - G_N)*D];
  float xv = x[lane];
  float h = b1[lane];
  #pragma unroll
  for (int k = 0; k < 32; ++k) {
    float xk = __shfl_sync(0xffffffffu, xv, k);
    h = fmaf(xk, w1[k*D + lane], h);
  }
  h = fmaxf(h, 0.f);
  float s = h * w2[lane];
  #pragma unroll
  for (int o = 16; o > 0; o >>= 1) s += __shfl_xor_sync(0xffffffffu, s, o);
  if (lane == 0) d_wgt[row] = 1.f/(1.f + expf(-(s + b2[0])));
}

__global__ void k_gfin() {
  int i = blockIdx.x*blockDim.x + threadIdx.x;
  if (i >= G_N*D) return;
  int g = i / D;
  d_gfin[i] = d_wgt[g]*d_gemb[i] + d_wgt[G_N + g]*d_gul[i];
}

__global__ void k_pred(const int* __restrict__ gin, const int* __restrict__ iin,
                       const float* __restrict__ w1, const float* __restrict__ b1,
                       const float* __restrict__ w2, const float* __restrict__ b2,
                       float* __restrict__ out) {
  int b = blockIdx.x*8 + (threadIdx.x >> 5);
  int lane = threadIdx.x & 31;
  if (b >= B_N) return;
  float e = d_gfin[gin[b]*D + lane] * d_iacc[iin[b]*D + lane];
  float z = 0.f;
  #pragma unroll
  for (int j = 0; j < 8; ++j) {
    float v = e * w1[lane*8 + j];
    #pragma unroll
    for (int o = 16; o > 0; o >>= 1) v += __shfl_xor_sync(0xffffffffu, v, o);
    if (lane == 0) z += fmaxf(v + b1[j], 0.f) * w2[j];
  }
  if (lane == 0) out[b] = 1.f/(1.f + expf(-(z + b2[0])));
}

// ----------------- host -----------------
template <typename T>
static T* symaddr(const void* sym) {
  void* p = nullptr;
  cudaGetSymbolAddress(&p, sym);
  return (T*)p;
}

extern "C" void kernel_launch(void* const* d_in, const int* in_sizes, int n_in,
                              void* d_out, int out_size) {
  const int*   gin       = (const int*)d_in[0];
  const int*   iin       = (const int*)d_in[1];
  const float* user_emb  = (const float*)d_in[2];
  const float* group_emb = (const float*)d_in[3];
  const float* item_emb  = (const float*)d_in[4];
  const int*   ui_rows   = (const int*)d_in[5];
  const int*   ui_cols   = (const int*)d_in[6];
  const float* ui_vals   = (const float*)d_in[7];
  const int*   gi_rows   = (const int*)d_in[8];
  const int*   gi_cols   = (const int*)d_in[9];
  const float* gi_vals   = (const float*)d_in[10];
  const float* ov_user   = (const float*)d_in[11];
  const float* ov_item   = (const float*)d_in[12];
  const int*   agu       = (const int*)d_in[13];
  const float* agm       = (const float*)d_in[14];
  const float* gate_w1   = (const float*)d_in[15];
  const float* gate_b1   = (const float*)d_in[16];
  const float* gate_w2   = (const float*)d_in[17];
  const float* gate_b2   = (const float*)d_in[18];
  const float* pred_w1   = (const float*)d_in[19];
  const float* pred_b1   = (const float*)d_in[20];
  const float* pred_w2   = (const float*)d_in[21];
  const float* pred_b2   = (const float*)d_in[22];
  float* out = (float*)d_out;

  cudaFuncSetAttribute(k_gemm, cudaFuncAttributeMaxDynamicSharedMemorySize, SMEM_MMA);

  float *p_ui0 = symaddr<float>(d_ui0), *p_ui1 = symaddr<float>(d_ui1);
  float *p_ui2 = symaddr<float>(d_ui2), *p_ui3 = symaddr<float>(d_ui3);
  float *p_gi0 = symaddr<float>(d_gi0), *p_gi1 = symaddr<float>(d_gi1);
  float *p_gi2 = symaddr<float>(d_gi2), *p_gi3 = symaddr<float>(d_gi3);
  float *p_cat  = symaddr<float>(d_cat), *p_cat2 = symaddr<float>(d_cat2);
  float *p_l1  = symaddr<float>(d_l1),  *p_l3  = symaddr<float>(d_l3);
  int *p_cnt  = symaddr<int>(d_cnt),  *p_off  = symaddr<int>(d_off),  *p_cur  = symaddr<int>(d_cur);
  int *p_cnt2 = symaddr<int>(d_cnt2), *p_off2 = symaddr<int>(d_off2), *p_cur2 = symaddr<int>(d_cur2);
  int *p_scol = symaddr<int>(d_scol), *p_scol2 = symaddr<int>(d_scol2);
  float *p_sval = symaddr<float>(d_sval), *p_sval2 = symaddr<float>(d_sval2);
  float *p_uemean = symaddr<float>(d_uemean), *p_iemean = symaddr<float>(d_iemean);
  float *p_iemb = symaddr<float>(d_iemb);
  float *p_parts = symaddr<float>(d_parts), *p_parts2 = symaddr<float>(d_parts2);
  float *p_t1 = symaddr<float>(d_t1), *p_accu = symaddr<float>(d_accu);
  float *p_it1 = symaddr<float>(d_it1), *p_iacc = symaddr<float>(d_iacc);

  const size_t PSU = (size_t)U_N * D;
  const size_t PSI = (size_t)I_N * D;
  dim3 gemm_u(CDIV(U_N, TILEM), KSU);
  dim3 gemm_i(CDIV(I_N, TILEM), KSI);

  cudaStream_t s1;
  cudaStreamCreateWithFlags(&s1, cudaStreamNonBlocking);
  cudaEvent_t ev_fork, ev_gicsr, ev_l1, ev_A, ev_mg, ev_C2;
  cudaEventCreateWithFlags(&ev_fork,  cudaEventDisableTiming);
  cudaEventCreateWithFlags(&ev_gicsr, cudaEventDisableTiming);
  cudaEventCreateWithFlags(&ev_l1,    cudaEventDisableTiming);
  cudaEventCreateWithFlags(&ev_A,     cudaEventDisableTiming);
  cudaEventCreateWithFlags(&ev_mg,    cudaEventDisableTiming);
  cudaEventCreateWithFlags(&ev_C2,    cudaEventDisableTiming);

  cudaEventRecord(ev_fork, 0);

  // ---- segment A1 (s0): launches #1..#4; #4 = representative GEMM for ncu ----
  k_copy_zero<<<CDIV((U_N+I_N)*D,256),256>>>(user_emb, U_N*D, item_emb, I_N*D, p_ui0, p_cnt, UI_N);
  k_count<<<CDIV(NNZ_UI,256),256>>>(ui_rows, NNZ_UI, p_cnt);
  k_scan<<<1,1024>>>(p_cnt, p_off, p_cur, UI_N);
  // HOOK (launch #4): steady-state MMA GEMM on ov_user, truncated K; output overwritten later.
  k_gemm<<<gemm_u,256,SMEM_MMA>>>(ov_user, ov_user, p_parts, PSU, U_N, 1536);

  // ---- segment B (s1): GI CSR build + l1 ----
  cudaStreamWaitEvent(s1, ev_fork, 0);
  k_zero_i<<<CDIV(GI_N,256),256,0,s1>>>(p_cnt2, GI_N);
  k_count<<<CDIV(NNZ_GI,256),256,0,s1>>>(gi_rows, NNZ_GI, p_cnt2);
  k_scan<<<1,1024,0,s1>>>(p_cnt2, p_off2, p_cur2, GI_N);
  k_scatter<<<CDIV(NNZ_GI,256),256,0,s1>>>(gi_rows, gi_cols, gi_vals, NNZ_GI, p_cur2, p_scol2, p_sval2);
  cudaEventRecord(ev_gicsr, s1);
  k_copy2<<<CDIV(GI_N*D,256),256,0,s1>>>(group_emb, G_N*D, item_emb, I_N*D, p_cat);
  k_spmm<<<CDIV(G_N,8),256,0,s1>>>(p_off2, p_scol2, p_sval2, p_cat, p_l1, G_N);
  cudaEventRecord(ev_l1, s1);

  // ---- segment A2 (s0): UI CSR + propagation ----
  k_scatter<<<CDIV(NNZ_UI,256),256>>>(ui_rows, ui_cols, ui_vals, NNZ_UI, p_cur, p_scol, p_sval);
  k_spmm<<<CDIV(UI_N,8),256>>>(p_off, p_scol, p_sval, p_ui0, p_ui1, UI_N);
  k_spmm<<<CDIV(UI_N,8),256>>>(p_off, p_scol, p_sval, p_ui1, p_ui2, UI_N);
  k_spmm<<<CDIV(UI_N,8),256>>>(p_off, p_scol, p_sval, p_ui2, p_ui3, UI_N);
  k_mean_ui<<<CDIV(UI_N*D,256),256>>>();
  cudaEventRecord(ev_A, 0);

  // ---- segment C (s1): user social GEMMs + group pooling ----
  cudaStreamWaitEvent(s1, ev_A, 0);
  k_gemm<<<gemm_u,256,SMEM_MMA,s1>>>(ov_user, p_uemean, p_parts, PSU, U_N, U_N);
  k_red<<<CDIV(U_N*D,256),256,0,s1>>>(p_t1, nullptr, nullptr, p_parts, PSU, U_N*D, KSU);
  k_gemm<<<gemm_u,256,SMEM_MMA,s1>>>(ov_user, p_t1, p_parts, PSU, U_N, U_N);
  k_red<<<CDIV(U_N*D,256),256,0,s1>>>(p_accu, p_uemean, p_t1, p_parts, PSU, U_N*D, KSU);
  k_gul<<<CDIV(G_N,8),256,0,s1>>>(agu, agm);

  // ---- segment D (s0): group-item propagation (overlaps C) ----
  k_copy2<<<CDIV(GI_N*D,256),256>>>(group_emb, G_N*D, p_iemean, I_N*D, p_gi0);
  cudaStreamWaitEvent(0, ev_gicsr, 0);
  k_spmm<<<CDIV(GI_N,8),256>>>(p_off2, p_scol2, p_sval2, p_gi0, p_gi1, GI_N);
  k_spmm<<<CDIV(GI_N,8),256>>>(p_off2, p_scol2, p_sval2, p_gi1, p_gi2, GI_N);
  k_spmm<<<CDIV(GI_N,8),256>>>(p_off2, p_scol2, p_sval2, p_gi2, p_gi3, GI_N);
  k_copy2<<<CDIV(GI_N*D,256),256>>>(group_emb, G_N*D, p_ui2 + U_N*D, I_N*D, p_cat2);
  k_spmm<<<CDIV(G_N,8),256>>>(p_off2, p_scol2, p_sval2, p_cat2, p_l3, G_N);
  cudaStreamWaitEvent(0, ev_l1, 0);
  k_mean_gi<<<CDIV(I_N*D,256),256>>>();
  cudaEventRecord(ev_mg, 0);

  // ---- segment E (s0): item social GEMMs ----
  k_gemm<<<gemm_i,256,SMEM_MMA>>>(ov_item, p_iemb, p_parts2, PSI, I_N, I_N);
  k_red<<<CDIV(I_N*D,256),256>>>(p_it1, nullptr, nullptr, p_parts2, PSI, I_N*D, KSI);
  k_gemm<<<gemm_i,256,SMEM_MMA>>>(ov_item, p_it1, p_parts2, PSI, I_N, I_N);
  k_red<<<CDIV(I_N*D,256),256>>>(p_iacc, p_iemb, p_it1, p_parts2, PSI, I_N*D, KSI);

  // ---- segment F (s1): gate ----
  cudaStreamWaitEvent(s1, ev_mg, 0);
  k_gate<<<CDIV(2*G_N,8),256,0,s1>>>(gate_w1, gate_b1, gate_w2, gate_b2);
  k_gfin<<<CDIV(G_N*D,256),256,0,s1>>>();
  cudaEventRecord(ev_C2, s1);

  // ---- segment G (s0): predict ----
  cudaStreamWaitEvent(0, ev_C2, 0);
  k_pred<<<CDIV(B_N,8),256>>>(gin, iin, pred_w1, pred_b1, pred_w2, pred_b2, out);
}